// round 1
// baseline (speedup 1.0000x reference)
#include <cuda_runtime.h>
#include <cuda_bf16.h>
#include <cstdint>

#define S_LEN   4096
#define HID     2048
#define NH      16
#define NKV     4
#define DH      128
#define QKV_LD  3072
#define Q_SCALE 0.08838834764831845f
#define INV_CAP (1.0f / 50.0f)
#define CAP     50.0f

// Scratch (device globals: no cudaMalloc allowed)
__device__ float g_qkv[(size_t)S_LEN * QKV_LD];   // [S, 3072]: Q(2048) | K(512) | V(512)
__device__ float g_attn[(size_t)S_LEN * HID];     // attention output [S, H*D]

// ---------------------------------------------------------------------------
// GEMM: C[m, col_off + n] = sum_k A[m,k] * B[n,k]   (A:[M,Kd], B:[N,Kd], both row-major)
// Tile 128x64x16, 256 threads, 8x4 register tile per thread.
// ---------------------------------------------------------------------------
__global__ __launch_bounds__(256) void gemm_bt_kernel(
    const float* __restrict__ A, const float* __restrict__ B, float* __restrict__ C,
    int M, int N, int Kd, int ldc, int col_off)
{
    __shared__ float As[16][128];   // transposed: As[k][m]
    __shared__ float Bs[16][64];    // transposed: Bs[k][n]

    const int tid  = threadIdx.x;
    const int bm   = blockIdx.y * 128;
    const int bn   = blockIdx.x * 64;
    const int tx   = tid & 15;      // col group (4 cols)
    const int ty   = tid >> 4;      // row group (8 rows)
    const int lrow = tid >> 2;      // 0..63
    const int lk   = (tid & 3) << 2; // 0,4,8,12

    const float* Ap = A + (size_t)(bm + lrow) * Kd + lk;
    const float* Bp = B + (size_t)(bn + lrow) * Kd + lk;

    float acc[8][4];
#pragma unroll
    for (int i = 0; i < 8; i++)
#pragma unroll
        for (int j = 0; j < 4; j++) acc[i][j] = 0.f;

    for (int k0 = 0; k0 < Kd; k0 += 16) {
        float4 a0 = *(const float4*)(Ap + k0);
        float4 a1 = *(const float4*)(Ap + (size_t)64 * Kd + k0);
        float4 b0 = *(const float4*)(Bp + k0);
        __syncthreads();
        As[lk + 0][lrow] = a0.x; As[lk + 1][lrow] = a0.y;
        As[lk + 2][lrow] = a0.z; As[lk + 3][lrow] = a0.w;
        As[lk + 0][lrow + 64] = a1.x; As[lk + 1][lrow + 64] = a1.y;
        As[lk + 2][lrow + 64] = a1.z; As[lk + 3][lrow + 64] = a1.w;
        Bs[lk + 0][lrow] = b0.x; Bs[lk + 1][lrow] = b0.y;
        Bs[lk + 2][lrow] = b0.z; Bs[lk + 3][lrow] = b0.w;
        __syncthreads();
#pragma unroll
        for (int kk = 0; kk < 16; kk++) {
            float a[8], b[4];
            *(float4*)&a[0] = *(const float4*)&As[kk][ty * 8];
            *(float4*)&a[4] = *(const float4*)&As[kk][ty * 8 + 4];
            *(float4*)&b[0] = *(const float4*)&Bs[kk][tx * 4];
#pragma unroll
            for (int i = 0; i < 8; i++)
#pragma unroll
                for (int j = 0; j < 4; j++)
                    acc[i][j] = fmaf(a[i], b[j], acc[i][j]);
        }
    }
#pragma unroll
    for (int i = 0; i < 8; i++) {
        float4 o = make_float4(acc[i][0], acc[i][1], acc[i][2], acc[i][3]);
        *(float4*)&C[(size_t)(bm + ty * 8 + i) * ldc + col_off + bn + tx * 4] = o;
    }
}

// ---------------------------------------------------------------------------
// RoPE (in place on g_qkv) + scale Q. One block per sequence position.
// heads 0..15 = Q heads (cols h*128), heads 16..19 = K heads (cols 2048 + g*128).
// ---------------------------------------------------------------------------
__global__ void rope_kernel(float* __restrict__ qkv,
                            const float* __restrict__ cosp,
                            const float* __restrict__ sinp)
{
    const int s = blockIdx.x;
    const float* c  = cosp + (size_t)s * DH;
    const float* sn = sinp + (size_t)s * DH;
    float* row = qkv + (size_t)s * QKV_LD;
    for (int i = threadIdx.x; i < 20 * 64; i += blockDim.x) {
        int hh = i >> 6;
        int d  = i & 63;
        int base = (hh < 16) ? hh * 128 : (2048 + (hh - 16) * 128);
        float x1 = row[base + d];
        float x2 = row[base + d + 64];
        float y1 = x1 * c[d]      - x2 * sn[d];
        float y2 = x2 * c[d + 64] + x1 * sn[d + 64];
        if (hh < 16) { y1 *= Q_SCALE; y2 *= Q_SCALE; }
        row[base + d]      = y1;
        row[base + d + 64] = y2;
    }
}

// ---------------------------------------------------------------------------
// Flash attention, fp32, tanh softcap, causal. 64 q-rows per CTA, 64-key tiles.
// 256 threads: score phase 4x4 per thread; PV phase 4 rows x 8 dims per thread.
// K/V share one smem buffer (K padded stride 129, V natural stride 128).
// ---------------------------------------------------------------------------
#define KS_LD 129
#define PS_LD 65
#define ATTN_SMEM_FLOATS (64 * 128 + 64 * KS_LD + 64 * PS_LD)

__global__ __launch_bounds__(256, 2) void attn_kernel(
    const float* __restrict__ qkv, float* __restrict__ out)
{
    extern __shared__ float smf[];
    float* Qs = smf;                      // [64][128]
    float* KV = Qs + 64 * 128;            // K: [64][129] / V: [64][128]
    float* Ps = KV + 64 * KS_LD;          // [64][65]

    const int tid = threadIdx.x;
    const int qb  = blockIdx.x;           // 0..63 (64 q rows each)
    const int h   = blockIdx.y;           // 0..15
    const int g   = h >> 2;               // GQA group (REP=4)

    const float* Qbase = qkv + h * DH;
    const float* Kbase = qkv + 2048 + g * DH;
    const float* Vbase = qkv + 2560 + g * DH;

    // Load Q tile [64][128]
    for (int i = tid; i < 64 * 32; i += 256) {
        int r  = i >> 5;
        int c4 = (i & 31) << 2;
        *(float4*)&Qs[r * 128 + c4] =
            *(const float4*)(Qbase + (size_t)(qb * 64 + r) * QKV_LD + c4);
    }

    const int tx = tid & 15;
    const int ty = tid >> 4;

    float m_i[4], l_i[4], acc[4][8];
#pragma unroll
    for (int i = 0; i < 4; i++) {
        m_i[i] = -1e30f; l_i[i] = 0.f;
#pragma unroll
        for (int j = 0; j < 8; j++) acc[i][j] = 0.f;
    }

    const int ntiles = qb + 1;
    for (int t = 0; t < ntiles; t++) {
        __syncthreads();  // guard KV/Ps from previous iteration's consumers
        // Load K tile (padded rows, scalar stores)
        for (int i = tid; i < 64 * 32; i += 256) {
            int r  = i >> 5;
            int c4 = (i & 31) << 2;
            float4 v = *(const float4*)(Kbase + (size_t)(t * 64 + r) * QKV_LD + c4);
            float* dst = &KV[r * KS_LD + c4];
            dst[0] = v.x; dst[1] = v.y; dst[2] = v.z; dst[3] = v.w;
        }
        __syncthreads();

        // Scores: sc[i][j] = q_row(ty*4+i) . k_col(tx*4+j)
        float sc[4][4];
#pragma unroll
        for (int i = 0; i < 4; i++)
#pragma unroll
            for (int j = 0; j < 4; j++) sc[i][j] = 0.f;
#pragma unroll 8
        for (int d = 0; d < 128; d++) {
            float a[4], b[4];
#pragma unroll
            for (int i = 0; i < 4; i++) a[i] = Qs[(ty * 4 + i) * 128 + d];
#pragma unroll
            for (int j = 0; j < 4; j++) b[j] = KV[(tx * 4 + j) * KS_LD + d];
#pragma unroll
            for (int i = 0; i < 4; i++)
#pragma unroll
                for (int j = 0; j < 4; j++)
                    sc[i][j] = fmaf(a[i], b[j], sc[i][j]);
        }

        // Softcap: tanh(x) = (e^{2x}-1)/(e^{2x}+1), then causal mask on diagonal tile
        const bool diag = (t == qb);
#pragma unroll
        for (int i = 0; i < 4; i++) {
#pragma unroll
            for (int j = 0; j < 4; j++) {
                float x = sc[i][j] * INV_CAP;
                x = fminf(fmaxf(x, -30.f), 30.f);
                float e = __expf(2.f * x);
                float v = __fdividef(e - 1.f, e + 1.f) * CAP;
                if (diag) {
                    int qr = (qb << 6) + ty * 4 + i;
                    int kc = (t << 6) + tx * 4 + j;
                    if (kc > qr) v = -1e30f;
                }
                sc[i][j] = v;
            }
        }

        // Row max across tile (16 lanes sharing a row live in one half-warp)
        float mt[4];
#pragma unroll
        for (int i = 0; i < 4; i++) {
            mt[i] = fmaxf(fmaxf(sc[i][0], sc[i][1]), fmaxf(sc[i][2], sc[i][3]));
#pragma unroll
            for (int off = 8; off; off >>= 1)
                mt[i] = fmaxf(mt[i], __shfl_xor_sync(0xffffffffu, mt[i], off));
        }

        float p[4][4], rs[4], alpha[4];
#pragma unroll
        for (int i = 0; i < 4; i++) {
            float mn = fmaxf(m_i[i], mt[i]);
            alpha[i] = __expf(m_i[i] - mn);
            m_i[i]   = mn;
            rs[i]    = 0.f;
#pragma unroll
            for (int j = 0; j < 4; j++) {
                p[i][j] = __expf(sc[i][j] - mn);
                rs[i] += p[i][j];
            }
#pragma unroll
            for (int off = 8; off; off >>= 1)
                rs[i] += __shfl_xor_sync(0xffffffffu, rs[i], off);
            l_i[i] = l_i[i] * alpha[i] + rs[i];
#pragma unroll
            for (int j = 0; j < 8; j++) acc[i][j] *= alpha[i];
#pragma unroll
            for (int j = 0; j < 4; j++)
                Ps[(ty * 4 + i) * PS_LD + tx * 4 + j] = p[i][j];
        }
        __syncthreads();  // all score-phase K reads done, Ps visible

        // Load V tile into the same buffer (natural stride 128, vector stores)
        for (int i = tid; i < 64 * 32; i += 256) {
            int r  = i >> 5;
            int c4 = (i & 31) << 2;
            *(float4*)&KV[r * 128 + c4] =
                *(const float4*)(Vbase + (size_t)(t * 64 + r) * QKV_LD + c4);
        }
        __syncthreads();

        // O += P * V   (thread: rows ty*4+i, dims tx*8 .. tx*8+7)
#pragma unroll 2
        for (int kk = 0; kk < 64; kk++) {
            float pp[4];
#pragma unroll
            for (int i = 0; i < 4; i++) pp[i] = Ps[(ty * 4 + i) * PS_LD + kk];
            float4 v0 = *(const float4*)&KV[kk * 128 + tx * 8];
            float4 v1 = *(const float4*)&KV[kk * 128 + tx * 8 + 4];
#pragma unroll
            for (int i = 0; i < 4; i++) {
                acc[i][0] = fmaf(pp[i], v0.x, acc[i][0]);
                acc[i][1] = fmaf(pp[i], v0.y, acc[i][1]);
                acc[i][2] = fmaf(pp[i], v0.z, acc[i][2]);
                acc[i][3] = fmaf(pp[i], v0.w, acc[i][3]);
                acc[i][4] = fmaf(pp[i], v1.x, acc[i][4]);
                acc[i][5] = fmaf(pp[i], v1.y, acc[i][5]);
                acc[i][6] = fmaf(pp[i], v1.z, acc[i][6]);
                acc[i][7] = fmaf(pp[i], v1.w, acc[i][7]);
            }
        }
    }

    // Epilogue: normalize and write [S, H*D]
#pragma unroll
    for (int i = 0; i < 4; i++) {
        float inv = __fdividef(1.f, l_i[i]);
        int r = (qb << 6) + ty * 4 + i;
        float4 o0 = make_float4(acc[i][0] * inv, acc[i][1] * inv,
                                acc[i][2] * inv, acc[i][3] * inv);
        float4 o1 = make_float4(acc[i][4] * inv, acc[i][5] * inv,
                                acc[i][6] * inv, acc[i][7] * inv);
        float* dst = out + (size_t)r * HID + h * DH + tx * 8;
        *(float4*)dst       = o0;
        *(float4*)(dst + 4) = o1;
    }
}

// ---------------------------------------------------------------------------
// Inputs (metadata order): hidden_states, cos, sin, attention_mask, wq, wk, wv, wo
// attention_mask is causal -> applied analytically, input unused.
// ---------------------------------------------------------------------------
extern "C" void kernel_launch(void* const* d_in, const int* in_sizes, int n_in,
                              void* d_out, int out_size)
{
    const float* hs   = (const float*)d_in[0];
    const float* cosp = (const float*)d_in[1];
    const float* sinp = (const float*)d_in[2];
    const float* wq   = (const float*)d_in[4];
    const float* wk   = (const float*)d_in[5];
    const float* wv   = (const float*)d_in[6];
    const float* wo   = (const float*)d_in[7];
    float* out = (float*)d_out;

    float* qkv = nullptr;
    float* attn = nullptr;
    cudaGetSymbolAddress((void**)&qkv, g_qkv);
    cudaGetSymbolAddress((void**)&attn, g_attn);

    dim3 blk(256);
    // QKV projections into one buffer [S, 3072]
    gemm_bt_kernel<<<dim3(2048 / 64, S_LEN / 128), blk>>>(hs, wq, qkv, S_LEN, 2048, HID, QKV_LD, 0);
    gemm_bt_kernel<<<dim3(512 / 64,  S_LEN / 128), blk>>>(hs, wk, qkv, S_LEN, 512,  HID, QKV_LD, 2048);
    gemm_bt_kernel<<<dim3(512 / 64,  S_LEN / 128), blk>>>(hs, wv, qkv, S_LEN, 512,  HID, QKV_LD, 2560);
    // RoPE + Q scale, in place
    rope_kernel<<<S_LEN, 256>>>(qkv, cosp, sinp);
    // Flash attention with softcap
    cudaFuncSetAttribute(attn_kernel, cudaFuncAttributeMaxDynamicSharedMemorySize,
                         ATTN_SMEM_FLOATS * (int)sizeof(float));
    attn_kernel<<<dim3(S_LEN / 64, NH), blk, ATTN_SMEM_FLOATS * sizeof(float)>>>(qkv, attn);
    // Output projection
    gemm_bt_kernel<<<dim3(2048 / 64, S_LEN / 128), blk>>>(attn, wo, out, S_LEN, HID, HID, HID, 0);
}

// round 3
// speedup vs baseline: 1.3387x; 1.3387x over previous
#include <cuda_runtime.h>
#include <cuda_bf16.h>
#include <cstdint>

#define S_LEN   4096
#define HID     2048
#define NH      16
#define NKV     4
#define DH      128
#define QKV_LD  3072
#define Q_SCALE 0.08838834764831845f
#define INV_CAP (1.0f / 50.0f)
#define CAP     50.0f

// Scratch (device globals: no cudaMalloc allowed)
__device__ float g_qkv[(size_t)S_LEN * QKV_LD];   // [S, 3072]: Q(2048) | K(512) | V(512)
__device__ float g_attn[(size_t)S_LEN * HID];     // attention output [S, H*D]

// ===========================================================================
// Helpers
// ===========================================================================
__device__ __forceinline__ uint32_t f2tf32(float x) {  // round-to-nearest tf32
    uint32_t o;
    asm("cvt.rna.tf32.f32 %0, %1;" : "=r"(o) : "f"(x));
    return o;
}

// mma.sync m16n8k8 tf32, f32 accumulate (plain sm_80+ PTX, works on sm_103 target)
__device__ __forceinline__ void mma_tf32(float* c, const uint32_t* a, const uint32_t* b) {
    asm volatile(
        "mma.sync.aligned.m16n8k8.row.col.f32.tf32.tf32.f32 "
        "{%0,%1,%2,%3}, {%4,%5,%6,%7}, {%8,%9}, {%0,%1,%2,%3};"
        : "+f"(c[0]), "+f"(c[1]), "+f"(c[2]), "+f"(c[3])
        : "r"(a[0]), "r"(a[1]), "r"(a[2]), "r"(a[3]), "r"(b[0]), "r"(b[1]));
}

// Fragment-layout smem word offsets.
// A tile (16m x 8k) = 128 words; lane block of 4 regs, XOR-swizzled by g*4.
__device__ __forceinline__ int a_word(int mi, int ki, int g, int e, int reg) {
    return mi * 512 + ki * 128 + ((g * 16 + e * 4 + reg) ^ (g * 4));
}
// B tile (8k x 8n) = 64 words + 4-word skew (stride 68); XOR bit1 by g>=4.
__device__ __forceinline__ int b_word(int ni, int ki, int g, int e, int reg) {
    return (ni * 4 + ki) * 68 + (((g * 4 + e) * 2 + reg) ^ ((g & 4) >> 1));
}

// ===========================================================================
// TF32 mma.sync GEMM: C[m, col_off+n] = sum_k A[m,k]*B[n,k]
// A:[M,Kd] row-major, B:[N,Kd] row-major. Tile 128x128, k-chunk 32.
// Double-buffered smem in fragment layout; 8 warps = 2(m) x 4(n).
// ===========================================================================
#define A_WORDS 4096            // 128x32 tf32
#define B_WORDS 4352            // 64 tiles * 68 words
#define GEMM_SMEM ((2 * A_WORDS + 2 * B_WORDS) * 4)

__global__ __launch_bounds__(256, 1) void gemm_mma(
    const float* __restrict__ A, const float* __restrict__ B, float* __restrict__ C,
    int Kd, int ldc, int col_off)
{
    extern __shared__ uint32_t smw[];
    uint32_t* Asm[2] = { smw, smw + A_WORDS };
    uint32_t* Bsm[2] = { smw + 2 * A_WORDS, smw + 2 * A_WORDS + B_WORDS };

    const int tid  = threadIdx.x;
    const int lane = tid & 31;
    const int warp = tid >> 5;
    const int wm   = warp >> 2;          // 0..1
    const int wn   = warp & 3;           // 0..3
    const int bm   = blockIdx.y * 128;
    const int bn   = blockIdx.x * 128;
    const int NC   = Kd / 32;

    // Loader geometry: thread covers rows {r, r+64}, col-f4 {c4*4, c4*4+16}
    const int r  = tid >> 2;
    const int c4 = tid & 3;
    const float* pA = A + (size_t)(bm + r) * Kd + c4 * 4;
    const float* pB = B + (size_t)(bn + r) * Kd + c4 * 4;

    // Precompute store descriptors for the 4 (rowsel, colsel) combos
    int aMi[2], aG[2], aHi[2], bNi[2], bG[2];
#pragma unroll
    for (int rs = 0; rs < 2; rs++) {
        int R = r + 64 * rs;
        aMi[rs] = R >> 4; aG[rs] = (R & 15) & 7; aHi[rs] = (R & 15) >> 3;
        bNi[rs] = R >> 3; bG[rs] = R & 7;
    }
    int kiSel[2], ccSel[2];
#pragma unroll
    for (int cs = 0; cs < 2; cs++) {
        int cb = c4 * 4 + 16 * cs;
        kiSel[cs] = cb >> 3; ccSel[cs] = (cb & 7) >> 2;
    }

    float acc[4][4][4];
#pragma unroll
    for (int i = 0; i < 4; i++)
#pragma unroll
        for (int j = 0; j < 4; j++)
#pragma unroll
            for (int e = 0; e < 4; e++) acc[i][j][e] = 0.f;

    // Compute-phase read offsets
    const int g = lane >> 2, t = lane & 3;
    const int aRd = (g * 16 + t * 4) ^ (g * 4);
    const int bRd = (lane * 2) ^ ((g & 4) >> 1);

    float4 ra[4], rb[4];

    // -------- prologue: chunk 0 --------
#pragma unroll
    for (int rs = 0; rs < 2; rs++)
#pragma unroll
        for (int cs = 0; cs < 2; cs++) {
            ra[rs * 2 + cs] = *(const float4*)(pA + (size_t)rs * 64 * Kd + cs * 16);
            rb[rs * 2 + cs] = *(const float4*)(pB + (size_t)rs * 64 * Kd + cs * 16);
        }
#pragma unroll
    for (int rs = 0; rs < 2; rs++)
#pragma unroll
        for (int cs = 0; cs < 2; cs++) {
            const float4 va = ra[rs * 2 + cs];
            const float4 vb = rb[rs * 2 + cs];
            const int ki = kiSel[cs];
            const int regA = aHi[rs] + 2 * ccSel[cs];
            const int regB = ccSel[cs];
            Asm[0][a_word(aMi[rs], ki, aG[rs], 0, regA)] = f2tf32(va.x);
            Asm[0][a_word(aMi[rs], ki, aG[rs], 1, regA)] = f2tf32(va.y);
            Asm[0][a_word(aMi[rs], ki, aG[rs], 2, regA)] = f2tf32(va.z);
            Asm[0][a_word(aMi[rs], ki, aG[rs], 3, regA)] = f2tf32(va.w);
            Bsm[0][b_word(bNi[rs], ki, bG[rs], 0, regB)] = f2tf32(vb.x);
            Bsm[0][b_word(bNi[rs], ki, bG[rs], 1, regB)] = f2tf32(vb.y);
            Bsm[0][b_word(bNi[rs], ki, bG[rs], 2, regB)] = f2tf32(vb.z);
            Bsm[0][b_word(bNi[rs], ki, bG[rs], 3, regB)] = f2tf32(vb.w);
        }
    __syncthreads();

    // -------- main loop --------
    for (int ic = 0; ic < NC; ic++) {
        const bool nb = (ic + 1 < NC);
        if (nb) {
            const size_t ko = (size_t)(ic + 1) * 32;
#pragma unroll
            for (int rs = 0; rs < 2; rs++)
#pragma unroll
                for (int cs = 0; cs < 2; cs++) {
                    ra[rs * 2 + cs] = *(const float4*)(pA + (size_t)rs * 64 * Kd + cs * 16 + ko);
                    rb[rs * 2 + cs] = *(const float4*)(pB + (size_t)rs * 64 * Kd + cs * 16 + ko);
                }
        }

        const uint32_t* Ab = Asm[ic & 1];
        const uint32_t* Bb = Bsm[ic & 1];
#pragma unroll
        for (int ki = 0; ki < 4; ki++) {
            uint32_t af[4][4], bf[4][2];
#pragma unroll
            for (int mi = 0; mi < 4; mi++) {
                uint4 q = *(const uint4*)(Ab + (wm * 4 + mi) * 512 + ki * 128 + aRd);
                af[mi][0] = q.x; af[mi][1] = q.y; af[mi][2] = q.z; af[mi][3] = q.w;
            }
#pragma unroll
            for (int ni = 0; ni < 4; ni++) {
                uint2 q = *(const uint2*)(Bb + ((wn * 4 + ni) * 4 + ki) * 68 + bRd);
                bf[ni][0] = q.x; bf[ni][1] = q.y;
            }
#pragma unroll
            for (int mi = 0; mi < 4; mi++)
#pragma unroll
                for (int ni = 0; ni < 4; ni++)
                    mma_tf32(acc[mi][ni], af[mi], bf[ni]);
        }

        if (nb) {
            uint32_t* Aw = Asm[(ic + 1) & 1];
            uint32_t* Bw = Bsm[(ic + 1) & 1];
#pragma unroll
            for (int rs = 0; rs < 2; rs++)
#pragma unroll
                for (int cs = 0; cs < 2; cs++) {
                    const float4 va = ra[rs * 2 + cs];
                    const float4 vb = rb[rs * 2 + cs];
                    const int ki = kiSel[cs];
                    const int regA = aHi[rs] + 2 * ccSel[cs];
                    const int regB = ccSel[cs];
                    Aw[a_word(aMi[rs], ki, aG[rs], 0, regA)] = f2tf32(va.x);
                    Aw[a_word(aMi[rs], ki, aG[rs], 1, regA)] = f2tf32(va.y);
                    Aw[a_word(aMi[rs], ki, aG[rs], 2, regA)] = f2tf32(va.z);
                    Aw[a_word(aMi[rs], ki, aG[rs], 3, regA)] = f2tf32(va.w);
                    Bw[b_word(bNi[rs], ki, bG[rs], 0, regB)] = f2tf32(vb.x);
                    Bw[b_word(bNi[rs], ki, bG[rs], 1, regB)] = f2tf32(vb.y);
                    Bw[b_word(bNi[rs], ki, bG[rs], 2, regB)] = f2tf32(vb.z);
                    Bw[b_word(bNi[rs], ki, bG[rs], 3, regB)] = f2tf32(vb.w);
                }
            __syncthreads();
        }
    }

    // -------- epilogue --------
#pragma unroll
    for (int mi = 0; mi < 4; mi++)
#pragma unroll
        for (int ni = 0; ni < 4; ni++) {
            const int row = bm + wm * 64 + mi * 16 + g;
            const int col = col_off + bn + wn * 32 + ni * 8 + t * 2;
            float* p0 = C + (size_t)row * ldc + col;
            float* p1 = C + (size_t)(row + 8) * ldc + col;
            *(float2*)p0 = make_float2(acc[mi][ni][0], acc[mi][ni][1]);
            *(float2*)p1 = make_float2(acc[mi][ni][2], acc[mi][ni][3]);
        }
}

// ---------------------------------------------------------------------------
// RoPE (in place on g_qkv) + scale Q. One block per sequence position.
// ---------------------------------------------------------------------------
__global__ void rope_kernel(float* __restrict__ qkv,
                            const float* __restrict__ cosp,
                            const float* __restrict__ sinp)
{
    const int s = blockIdx.x;
    const float* c  = cosp + (size_t)s * DH;
    const float* sn = sinp + (size_t)s * DH;
    float* row = qkv + (size_t)s * QKV_LD;
    for (int i = threadIdx.x; i < 20 * 64; i += blockDim.x) {
        int hh = i >> 6;
        int d  = i & 63;
        int base = (hh < 16) ? hh * 128 : (2048 + (hh - 16) * 128);
        float x1 = row[base + d];
        float x2 = row[base + d + 64];
        float y1 = x1 * c[d]      - x2 * sn[d];
        float y2 = x2 * c[d + 64] + x1 * sn[d + 64];
        if (hh < 16) { y1 *= Q_SCALE; y2 *= Q_SCALE; }
        row[base + d]      = y1;
        row[base + d + 64] = y2;
    }
}

// ---------------------------------------------------------------------------
// Flash attention, fp32, tanh softcap, causal. 64 q-rows per CTA, 64-key tiles.
// ---------------------------------------------------------------------------
#define KS_LD 129
#define PS_LD 65
#define ATTN_SMEM_FLOATS (64 * 128 + 64 * KS_LD + 64 * PS_LD)

__global__ __launch_bounds__(256, 2) void attn_kernel(
    const float* __restrict__ qkv, float* __restrict__ out)
{
    extern __shared__ float smf[];
    float* Qs = smf;                      // [64][128]
    float* KV = Qs + 64 * 128;            // K: [64][129] / V: [64][128]
    float* Ps = KV + 64 * KS_LD;          // [64][65]

    const int tid = threadIdx.x;
    const int qb  = blockIdx.x;
    const int h   = blockIdx.y;
    const int g   = h >> 2;

    const float* Qbase = qkv + h * DH;
    const float* Kbase = qkv + 2048 + g * DH;
    const float* Vbase = qkv + 2560 + g * DH;

    for (int i = tid; i < 64 * 32; i += 256) {
        int r  = i >> 5;
        int c4 = (i & 31) << 2;
        *(float4*)&Qs[r * 128 + c4] =
            *(const float4*)(Qbase + (size_t)(qb * 64 + r) * QKV_LD + c4);
    }

    const int tx = tid & 15;
    const int ty = tid >> 4;

    float m_i[4], l_i[4], acc[4][8];
#pragma unroll
    for (int i = 0; i < 4; i++) {
        m_i[i] = -1e30f; l_i[i] = 0.f;
#pragma unroll
        for (int j = 0; j < 8; j++) acc[i][j] = 0.f;
    }

    const int ntiles = qb + 1;
    for (int t = 0; t < ntiles; t++) {
        __syncthreads();
        for (int i = tid; i < 64 * 32; i += 256) {
            int r  = i >> 5;
            int c4 = (i & 31) << 2;
            float4 v = *(const float4*)(Kbase + (size_t)(t * 64 + r) * QKV_LD + c4);
            float* dst = &KV[r * KS_LD + c4];
            dst[0] = v.x; dst[1] = v.y; dst[2] = v.z; dst[3] = v.w;
        }
        __syncthreads();

        float sc[4][4];
#pragma unroll
        for (int i = 0; i < 4; i++)
#pragma unroll
            for (int j = 0; j < 4; j++) sc[i][j] = 0.f;
#pragma unroll 8
        for (int d = 0; d < 128; d++) {
            float a[4], b[4];
#pragma unroll
            for (int i = 0; i < 4; i++) a[i] = Qs[(ty * 4 + i) * 128 + d];
#pragma unroll
            for (int j = 0; j < 4; j++) b[j] = KV[(tx * 4 + j) * KS_LD + d];
#pragma unroll
            for (int i = 0; i < 4; i++)
#pragma unroll
                for (int j = 0; j < 4; j++)
                    sc[i][j] = fmaf(a[i], b[j], sc[i][j]);
        }

        const bool diag = (t == qb);
#pragma unroll
        for (int i = 0; i < 4; i++) {
#pragma unroll
            for (int j = 0; j < 4; j++) {
                float x = sc[i][j] * INV_CAP;
                x = fminf(fmaxf(x, -30.f), 30.f);
                float e = __expf(2.f * x);
                float v = __fdividef(e - 1.f, e + 1.f) * CAP;
                if (diag) {
                    int qr = (qb << 6) + ty * 4 + i;
                    int kc = (t << 6) + tx * 4 + j;
                    if (kc > qr) v = -1e30f;
                }
                sc[i][j] = v;
            }
        }

        float mt[4];
#pragma unroll
        for (int i = 0; i < 4; i++) {
            mt[i] = fmaxf(fmaxf(sc[i][0], sc[i][1]), fmaxf(sc[i][2], sc[i][3]));
#pragma unroll
            for (int off = 8; off; off >>= 1)
                mt[i] = fmaxf(mt[i], __shfl_xor_sync(0xffffffffu, mt[i], off));
        }

        float p[4][4], rs[4], alpha[4];
#pragma unroll
        for (int i = 0; i < 4; i++) {
            float mn = fmaxf(m_i[i], mt[i]);
            alpha[i] = __expf(m_i[i] - mn);
            m_i[i]   = mn;
            rs[i]    = 0.f;
#pragma unroll
            for (int j = 0; j < 4; j++) {
                p[i][j] = __expf(sc[i][j] - mn);
                rs[i] += p[i][j];
            }
#pragma unroll
            for (int off = 8; off; off >>= 1)
                rs[i] += __shfl_xor_sync(0xffffffffu, rs[i], off);
            l_i[i] = l_i[i] * alpha[i] + rs[i];
#pragma unroll
            for (int j = 0; j < 8; j++) acc[i][j] *= alpha[i];
#pragma unroll
            for (int j = 0; j < 4; j++)
                Ps[(ty * 4 + i) * PS_LD + tx * 4 + j] = p[i][j];
        }
        __syncthreads();

        for (int i = tid; i < 64 * 32; i += 256) {
            int r  = i >> 5;
            int c4 = (i & 31) << 2;
            *(float4*)&KV[r * 128 + c4] =
                *(const float4*)(Vbase + (size_t)(t * 64 + r) * QKV_LD + c4);
        }
        __syncthreads();

#pragma unroll 2
        for (int kk = 0; kk < 64; kk++) {
            float pp[4];
#pragma unroll
            for (int i = 0; i < 4; i++) pp[i] = Ps[(ty * 4 + i) * PS_LD + kk];
            float4 v0 = *(const float4*)&KV[kk * 128 + tx * 8];
            float4 v1 = *(const float4*)&KV[kk * 128 + tx * 8 + 4];
#pragma unroll
            for (int i = 0; i < 4; i++) {
                acc[i][0] = fmaf(pp[i], v0.x, acc[i][0]);
                acc[i][1] = fmaf(pp[i], v0.y, acc[i][1]);
                acc[i][2] = fmaf(pp[i], v0.z, acc[i][2]);
                acc[i][3] = fmaf(pp[i], v0.w, acc[i][3]);
                acc[i][4] = fmaf(pp[i], v1.x, acc[i][4]);
                acc[i][5] = fmaf(pp[i], v1.y, acc[i][5]);
                acc[i][6] = fmaf(pp[i], v1.z, acc[i][6]);
                acc[i][7] = fmaf(pp[i], v1.w, acc[i][7]);
            }
        }
    }

#pragma unroll
    for (int i = 0; i < 4; i++) {
        float inv = __fdividef(1.f, l_i[i]);
        int r = (qb << 6) + ty * 4 + i;
        float4 o0 = make_float4(acc[i][0] * inv, acc[i][1] * inv,
                                acc[i][2] * inv, acc[i][3] * inv);
        float4 o1 = make_float4(acc[i][4] * inv, acc[i][5] * inv,
                                acc[i][6] * inv, acc[i][7] * inv);
        float* dst = out + (size_t)r * HID + h * DH + tx * 8;
        *(float4*)dst       = o0;
        *(float4*)(dst + 4) = o1;
    }
}

// ---------------------------------------------------------------------------
// Inputs (metadata order): hidden_states, cos, sin, attention_mask, wq, wk, wv, wo
// ---------------------------------------------------------------------------
extern "C" void kernel_launch(void* const* d_in, const int* in_sizes, int n_in,
                              void* d_out, int out_size)
{
    const float* hs   = (const float*)d_in[0];
    const float* cosp = (const float*)d_in[1];
    const float* sinp = (const float*)d_in[2];
    const float* wq   = (const float*)d_in[4];
    const float* wk   = (const float*)d_in[5];
    const float* wv   = (const float*)d_in[6];
    const float* wo   = (const float*)d_in[7];
    float* out = (float*)d_out;

    float* qkv = nullptr;
    float* attn = nullptr;
    cudaGetSymbolAddress((void**)&qkv, g_qkv);
    cudaGetSymbolAddress((void**)&attn, g_attn);

    cudaFuncSetAttribute(gemm_mma, cudaFuncAttributeMaxDynamicSharedMemorySize, GEMM_SMEM);
    cudaFuncSetAttribute(attn_kernel, cudaFuncAttributeMaxDynamicSharedMemorySize,
                         ATTN_SMEM_FLOATS * (int)sizeof(float));

    dim3 blk(256);
    // QKV projections into one buffer [S, 3072] (tf32 mma.sync)
    gemm_mma<<<dim3(2048 / 128, S_LEN / 128), blk, GEMM_SMEM>>>(hs, wq, qkv, HID, QKV_LD, 0);
    gemm_mma<<<dim3(512 / 128,  S_LEN / 128), blk, GEMM_SMEM>>>(hs, wk, qkv, HID, QKV_LD, 2048);
    gemm_mma<<<dim3(512 / 128,  S_LEN / 128), blk, GEMM_SMEM>>>(hs, wv, qkv, HID, QKV_LD, 2560);
    // RoPE + Q scale, in place
    rope_kernel<<<S_LEN, 256>>>(qkv, cosp, sinp);
    // Flash attention with softcap (fp32)
    attn_kernel<<<dim3(S_LEN / 64, NH), blk, ATTN_SMEM_FLOATS * sizeof(float)>>>(qkv, attn);
    // Output projection (tf32 mma.sync)
    gemm_mma<<<dim3(2048 / 128, S_LEN / 128), blk, GEMM_SMEM>>>(attn, wo, out, HID, HID, 0);
}

// round 4
// speedup vs baseline: 2.4169x; 1.8054x over previous
#include <cuda_runtime.h>
#include <cuda_bf16.h>
#include <cstdint>

#define S_LEN   4096
#define HID     2048
#define NH      16
#define NKV     4
#define DH      128
#define QKV_LD  3072
#define Q_SCALE 0.08838834764831845f
#define INV_CAP (1.0f / 50.0f)
#define CAP     50.0f

// Scratch (device globals: no cudaMalloc allowed)
__device__ float g_qkv[(size_t)S_LEN * QKV_LD];   // [S, 3072]: Q(2048) | K(512) | V(512)
__device__ float g_attn[(size_t)S_LEN * HID];     // attention output [S, H*D]

// ===========================================================================
// Helpers
// ===========================================================================
__device__ __forceinline__ uint32_t f2tf32(float x) {  // round-to-nearest tf32
    uint32_t o;
    asm("cvt.rna.tf32.f32 %0, %1;" : "=r"(o) : "f"(x));
    return o;
}

// mma.sync m16n8k8 tf32, f32 accumulate
__device__ __forceinline__ void mma_tf32(float* c, const uint32_t* a, const uint32_t* b) {
    asm volatile(
        "mma.sync.aligned.m16n8k8.row.col.f32.tf32.tf32.f32 "
        "{%0,%1,%2,%3}, {%4,%5,%6,%7}, {%8,%9}, {%0,%1,%2,%3};"
        : "+f"(c[0]), "+f"(c[1]), "+f"(c[2]), "+f"(c[3])
        : "r"(a[0]), "r"(a[1]), "r"(a[2]), "r"(a[3]), "r"(b[0]), "r"(b[1]));
}

// Fragment-layout smem word offsets (validated in gemm_mma, Round 3).
__device__ __forceinline__ int a_word(int mi, int ki, int g, int e, int reg) {
    return mi * 512 + ki * 128 + ((g * 16 + e * 4 + reg) ^ (g * 4));
}
__device__ __forceinline__ int b_word(int ni, int ki, int g, int e, int reg) {
    return (ni * 4 + ki) * 68 + (((g * 4 + e) * 2 + reg) ^ ((g & 4) >> 1));
}

// ===========================================================================
// TF32 mma.sync GEMM (unchanged from Round 3)
// ===========================================================================
#define A_WORDS 4096
#define B_WORDS 4352
#define GEMM_SMEM ((2 * A_WORDS + 2 * B_WORDS) * 4)

__global__ __launch_bounds__(256, 1) void gemm_mma(
    const float* __restrict__ A, const float* __restrict__ B, float* __restrict__ C,
    int Kd, int ldc, int col_off)
{
    extern __shared__ uint32_t smw[];
    uint32_t* Asm[2] = { smw, smw + A_WORDS };
    uint32_t* Bsm[2] = { smw + 2 * A_WORDS, smw + 2 * A_WORDS + B_WORDS };

    const int tid  = threadIdx.x;
    const int lane = tid & 31;
    const int warp = tid >> 5;
    const int wm   = warp >> 2;
    const int wn   = warp & 3;
    const int bm   = blockIdx.y * 128;
    const int bn   = blockIdx.x * 128;
    const int NC   = Kd / 32;

    const int r  = tid >> 2;
    const int c4 = tid & 3;
    const float* pA = A + (size_t)(bm + r) * Kd + c4 * 4;
    const float* pB = B + (size_t)(bn + r) * Kd + c4 * 4;

    int aMi[2], aG[2], aHi[2], bNi[2], bG[2];
#pragma unroll
    for (int rs = 0; rs < 2; rs++) {
        int R = r + 64 * rs;
        aMi[rs] = R >> 4; aG[rs] = (R & 15) & 7; aHi[rs] = (R & 15) >> 3;
        bNi[rs] = R >> 3; bG[rs] = R & 7;
    }
    int kiSel[2], ccSel[2];
#pragma unroll
    for (int cs = 0; cs < 2; cs++) {
        int cb = c4 * 4 + 16 * cs;
        kiSel[cs] = cb >> 3; ccSel[cs] = (cb & 7) >> 2;
    }

    float acc[4][4][4];
#pragma unroll
    for (int i = 0; i < 4; i++)
#pragma unroll
        for (int j = 0; j < 4; j++)
#pragma unroll
            for (int e = 0; e < 4; e++) acc[i][j][e] = 0.f;

    const int g = lane >> 2, t = lane & 3;
    const int aRd = (g * 16 + t * 4) ^ (g * 4);
    const int bRd = (lane * 2) ^ ((g & 4) >> 1);

    float4 ra[4], rb[4];

#pragma unroll
    for (int rs = 0; rs < 2; rs++)
#pragma unroll
        for (int cs = 0; cs < 2; cs++) {
            ra[rs * 2 + cs] = *(const float4*)(pA + (size_t)rs * 64 * Kd + cs * 16);
            rb[rs * 2 + cs] = *(const float4*)(pB + (size_t)rs * 64 * Kd + cs * 16);
        }
#pragma unroll
    for (int rs = 0; rs < 2; rs++)
#pragma unroll
        for (int cs = 0; cs < 2; cs++) {
            const float4 va = ra[rs * 2 + cs];
            const float4 vb = rb[rs * 2 + cs];
            const int ki = kiSel[cs];
            const int regA = aHi[rs] + 2 * ccSel[cs];
            const int regB = ccSel[cs];
            Asm[0][a_word(aMi[rs], ki, aG[rs], 0, regA)] = f2tf32(va.x);
            Asm[0][a_word(aMi[rs], ki, aG[rs], 1, regA)] = f2tf32(va.y);
            Asm[0][a_word(aMi[rs], ki, aG[rs], 2, regA)] = f2tf32(va.z);
            Asm[0][a_word(aMi[rs], ki, aG[rs], 3, regA)] = f2tf32(va.w);
            Bsm[0][b_word(bNi[rs], ki, bG[rs], 0, regB)] = f2tf32(vb.x);
            Bsm[0][b_word(bNi[rs], ki, bG[rs], 1, regB)] = f2tf32(vb.y);
            Bsm[0][b_word(bNi[rs], ki, bG[rs], 2, regB)] = f2tf32(vb.z);
            Bsm[0][b_word(bNi[rs], ki, bG[rs], 3, regB)] = f2tf32(vb.w);
        }
    __syncthreads();

    for (int ic = 0; ic < NC; ic++) {
        const bool nb = (ic + 1 < NC);
        if (nb) {
            const size_t ko = (size_t)(ic + 1) * 32;
#pragma unroll
            for (int rs = 0; rs < 2; rs++)
#pragma unroll
                for (int cs = 0; cs < 2; cs++) {
                    ra[rs * 2 + cs] = *(const float4*)(pA + (size_t)rs * 64 * Kd + cs * 16 + ko);
                    rb[rs * 2 + cs] = *(const float4*)(pB + (size_t)rs * 64 * Kd + cs * 16 + ko);
                }
        }

        const uint32_t* Ab = Asm[ic & 1];
        const uint32_t* Bb = Bsm[ic & 1];
#pragma unroll
        for (int ki = 0; ki < 4; ki++) {
            uint32_t af[4][4], bf[4][2];
#pragma unroll
            for (int mi = 0; mi < 4; mi++) {
                uint4 q = *(const uint4*)(Ab + (wm * 4 + mi) * 512 + ki * 128 + aRd);
                af[mi][0] = q.x; af[mi][1] = q.y; af[mi][2] = q.z; af[mi][3] = q.w;
            }
#pragma unroll
            for (int ni = 0; ni < 4; ni++) {
                uint2 q = *(const uint2*)(Bb + ((wn * 4 + ni) * 4 + ki) * 68 + bRd);
                bf[ni][0] = q.x; bf[ni][1] = q.y;
            }
#pragma unroll
            for (int mi = 0; mi < 4; mi++)
#pragma unroll
                for (int ni = 0; ni < 4; ni++)
                    mma_tf32(acc[mi][ni], af[mi], bf[ni]);
        }

        if (nb) {
            uint32_t* Aw = Asm[(ic + 1) & 1];
            uint32_t* Bw = Bsm[(ic + 1) & 1];
#pragma unroll
            for (int rs = 0; rs < 2; rs++)
#pragma unroll
                for (int cs = 0; cs < 2; cs++) {
                    const float4 va = ra[rs * 2 + cs];
                    const float4 vb = rb[rs * 2 + cs];
                    const int ki = kiSel[cs];
                    const int regA = aHi[rs] + 2 * ccSel[cs];
                    const int regB = ccSel[cs];
                    Aw[a_word(aMi[rs], ki, aG[rs], 0, regA)] = f2tf32(va.x);
                    Aw[a_word(aMi[rs], ki, aG[rs], 1, regA)] = f2tf32(va.y);
                    Aw[a_word(aMi[rs], ki, aG[rs], 2, regA)] = f2tf32(va.z);
                    Aw[a_word(aMi[rs], ki, aG[rs], 3, regA)] = f2tf32(va.w);
                    Bw[b_word(bNi[rs], ki, bG[rs], 0, regB)] = f2tf32(vb.x);
                    Bw[b_word(bNi[rs], ki, bG[rs], 1, regB)] = f2tf32(vb.y);
                    Bw[b_word(bNi[rs], ki, bG[rs], 2, regB)] = f2tf32(vb.z);
                    Bw[b_word(bNi[rs], ki, bG[rs], 3, regB)] = f2tf32(vb.w);
                }
            __syncthreads();
        }
    }

#pragma unroll
    for (int mi = 0; mi < 4; mi++)
#pragma unroll
        for (int ni = 0; ni < 4; ni++) {
            const int row = bm + wm * 64 + mi * 16 + g;
            const int col = col_off + bn + wn * 32 + ni * 8 + t * 2;
            float* p0 = C + (size_t)row * ldc + col;
            float* p1 = C + (size_t)(row + 8) * ldc + col;
            *(float2*)p0 = make_float2(acc[mi][ni][0], acc[mi][ni][1]);
            *(float2*)p1 = make_float2(acc[mi][ni][2], acc[mi][ni][3]);
        }
}

// ---------------------------------------------------------------------------
// RoPE (in place on g_qkv) + scale Q.
// ---------------------------------------------------------------------------
__global__ void rope_kernel(float* __restrict__ qkv,
                            const float* __restrict__ cosp,
                            const float* __restrict__ sinp)
{
    const int s = blockIdx.x;
    const float* c  = cosp + (size_t)s * DH;
    const float* sn = sinp + (size_t)s * DH;
    float* row = qkv + (size_t)s * QKV_LD;
    for (int i = threadIdx.x; i < 20 * 64; i += blockDim.x) {
        int hh = i >> 6;
        int d  = i & 63;
        int base = (hh < 16) ? hh * 128 : (2048 + (hh - 16) * 128);
        float x1 = row[base + d];
        float x2 = row[base + d + 64];
        float y1 = x1 * c[d]      - x2 * sn[d];
        float y2 = x2 * c[d + 64] + x1 * sn[d + 64];
        if (hh < 16) { y1 *= Q_SCALE; y2 *= Q_SCALE; }
        row[base + d]      = y1;
        row[base + d + 64] = y2;
    }
}

// ===========================================================================
// Flash attention with tf32 mma.sync. BM=128 q rows, BN=64 keys, 8 warps.
// Warp w owns m16 row-slab [w*16, w*16+16) -> warp-local softmax.
// Q in A-frag layout (once), K in B-frag layout, V transposed into B-frag
// layout, P round-trips through smem in A-frag layout.
// ===========================================================================
#define BM 128
#define BN 64
#define AQ_OFF 0                       // Q: 128x128 = 16384 words
#define AK_OFF 16384                   // K: 8 n-tiles x 16 k-steps x 68 = 8704
#define AV_OFF (16384 + 8704)          // V^T: 16 n-tiles x 8 k-steps x 68 = 8704
#define AP_OFF (16384 + 2 * 8704)      // P: 128x64 = 8192 words
#define ATTN_WORDS (16384 + 2 * 8704 + 8192)
#define ATTN_SMEM (ATTN_WORDS * 4)

__global__ __launch_bounds__(256, 1) void attn_mma(
    const float* __restrict__ qkv, float* __restrict__ out)
{
    extern __shared__ uint32_t sw[];
    uint32_t* Qs = sw + AQ_OFF;
    uint32_t* Ks = sw + AK_OFF;
    uint32_t* Vs = sw + AV_OFF;
    uint32_t* Ps = sw + AP_OFF;

    const int tid  = threadIdx.x;
    const int lane = tid & 31;
    const int warp = tid >> 5;
    const int qb   = (int)gridDim.x - 1 - (int)blockIdx.x;  // big tiles first
    const int h    = blockIdx.y;
    const int kvg  = h >> 2;

    const int g = lane >> 2, t = lane & 3;
    const int aRd = (g * 16 + t * 4) ^ (g * 4);
    const int bRd = (lane * 2) ^ ((g & 4) >> 1);

    const float* Qg = qkv + h * DH;
    const float* Kg = qkv + 2048 + kvg * DH;
    const float* Vg = qkv + 2560 + kvg * DH;

    // ---- Q tile -> A-frag layout (persistent across key tiles) ----
    for (int i = tid; i < BM * 32; i += 256) {
        int r = i >> 5, c4 = i & 31;
        float4 v = *(const float4*)(Qg + (size_t)(qb * BM + r) * QKV_LD + c4 * 4);
        int mi = r >> 4, rr = r & 15, hi = rr >> 3, gg = rr & 7;
        int base = mi * 2048;
        float vv[4] = { v.x, v.y, v.z, v.w };
#pragma unroll
        for (int e = 0; e < 4; e++) {
            int c = c4 * 4 + e;
            int ki = c >> 3, cc = c & 7;
            int reg = hi + 2 * (cc >> 2);
            Qs[base + ki * 128 + ((gg * 16 + (cc & 3) * 4 + reg) ^ (gg * 4))] = f2tf32(vv[e]);
        }
    }

    float oacc[16][4];
#pragma unroll
    for (int i = 0; i < 16; i++)
#pragma unroll
        for (int e = 0; e < 4; e++) oacc[i][e] = 0.f;
    float m0 = -1e30f, m1 = -1e30f, l0 = 0.f, l1 = 0.f;

    const int qr0 = qb * BM + warp * 16 + g;   // row of c0,c1
    const int ntiles = 2 * qb + 2;

    for (int kt = 0; kt < ntiles; kt++) {
        __syncthreads();
        // ---- K tile -> B-frag layout ----
        for (int i = tid; i < BN * 32; i += 256) {
            int r = i >> 5, c4 = i & 31;
            float4 v = *(const float4*)(Kg + (size_t)(kt * BN + r) * QKV_LD + c4 * 4);
            int nI = r >> 3, gg = r & 7;
            int c0 = c4 * 4;
            int ki = c0 >> 3, reg = (c0 & 7) >> 2;
            int base = (nI * 16 + ki) * 68;
            float vv[4] = { v.x, v.y, v.z, v.w };
#pragma unroll
            for (int e = 0; e < 4; e++)
                Ks[base + (((gg * 4 + e) * 2 + reg) ^ ((gg & 4) >> 1))] = f2tf32(vv[e]);
        }
        // ---- V tile (transposed) -> B-frag layout: n=dim, k=key ----
        for (int i = tid; i < BN * 32; i += 256) {
            int r = i >> 5, c4 = i & 31;      // r = key, c4*4 = dim
            float4 v = *(const float4*)(Vg + (size_t)(kt * BN + r) * QKV_LD + c4 * 4);
            int ki = r >> 3, reg = (r & 7) >> 2, tt = r & 3;
            float vv[4] = { v.x, v.y, v.z, v.w };
#pragma unroll
            for (int e = 0; e < 4; e++) {
                int d = c4 * 4 + e;
                int ni = d >> 3, gg = d & 7;
                Vs[(ni * 8 + ki) * 68 + (((gg * 4 + tt) * 2 + reg) ^ ((gg & 4) >> 1))] = f2tf32(vv[e]);
            }
        }
        __syncthreads();

        // ---- QK: S[m16 x 64] per warp ----
        float acc[8][4];
#pragma unroll
        for (int nt = 0; nt < 8; nt++)
#pragma unroll
            for (int e = 0; e < 4; e++) acc[nt][e] = 0.f;
#pragma unroll 4
        for (int ki = 0; ki < 16; ki++) {
            uint4 qa = *(const uint4*)(Qs + warp * 2048 + ki * 128 + aRd);
            uint32_t af[4] = { qa.x, qa.y, qa.z, qa.w };
#pragma unroll
            for (int nt = 0; nt < 8; nt++) {
                uint2 kb = *(const uint2*)(Ks + (nt * 16 + ki) * 68 + bRd);
                uint32_t bf[2] = { kb.x, kb.y };
                mma_tf32(acc[nt], af, bf);
            }
        }

        // ---- softcap + causal mask ----
        const bool diag = (kt >= 2 * qb);
        float mt0 = -1e30f, mt1 = -1e30f;
#pragma unroll
        for (int nt = 0; nt < 8; nt++) {
#pragma unroll
            for (int e = 0; e < 4; e++) {
                float x = acc[nt][e] * INV_CAP;
                x = fminf(fmaxf(x, -20.f), 20.f);
                float ex = __expf(2.f * x);
                float v = __fdividef(ex - 1.f, ex + 1.f) * CAP;
                if (diag) {
                    int kc = kt * BN + nt * 8 + 2 * t + (e & 1);
                    int qr = qr0 + ((e >> 1) << 3);
                    if (kc > qr) v = -1e30f;
                }
                acc[nt][e] = v;
                if (e < 2) mt0 = fmaxf(mt0, v); else mt1 = fmaxf(mt1, v);
            }
        }
        mt0 = fmaxf(mt0, __shfl_xor_sync(0xffffffffu, mt0, 1));
        mt0 = fmaxf(mt0, __shfl_xor_sync(0xffffffffu, mt0, 2));
        mt1 = fmaxf(mt1, __shfl_xor_sync(0xffffffffu, mt1, 1));
        mt1 = fmaxf(mt1, __shfl_xor_sync(0xffffffffu, mt1, 2));

        const float mn0 = fmaxf(m0, mt0), mn1 = fmaxf(m1, mt1);
        const float al0 = __expf(m0 - mn0), al1 = __expf(m1 - mn1);
        m0 = mn0; m1 = mn1;

        float rs0 = 0.f, rs1 = 0.f;
#pragma unroll
        for (int nt = 0; nt < 8; nt++) {
            acc[nt][0] = __expf(acc[nt][0] - mn0);
            acc[nt][1] = __expf(acc[nt][1] - mn0);
            acc[nt][2] = __expf(acc[nt][2] - mn1);
            acc[nt][3] = __expf(acc[nt][3] - mn1);
            rs0 += acc[nt][0] + acc[nt][1];
            rs1 += acc[nt][2] + acc[nt][3];
        }
        rs0 += __shfl_xor_sync(0xffffffffu, rs0, 1);
        rs0 += __shfl_xor_sync(0xffffffffu, rs0, 2);
        rs1 += __shfl_xor_sync(0xffffffffu, rs1, 1);
        rs1 += __shfl_xor_sync(0xffffffffu, rs1, 2);
        l0 = l0 * al0 + rs0;
        l1 = l1 * al1 + rs1;

#pragma unroll
        for (int ni = 0; ni < 16; ni++) {
            oacc[ni][0] *= al0; oacc[ni][1] *= al0;
            oacc[ni][2] *= al1; oacc[ni][3] *= al1;
        }

        // ---- P (C-frag) -> smem in A-frag layout ----
        {
            const int ccsel = (t >= 2) ? 2 : 0;
            const int t0 = (2 * t) & 3, t1 = (2 * t + 1) & 3;
            const int pw = warp * 1024;
#pragma unroll
            for (int nt = 0; nt < 8; nt++) {
                int base = pw + nt * 128;
                Ps[base + ((g * 16 + t0 * 4 + ccsel)     ^ (g * 4))] = f2tf32(acc[nt][0]);
                Ps[base + ((g * 16 + t1 * 4 + ccsel)     ^ (g * 4))] = f2tf32(acc[nt][1]);
                Ps[base + ((g * 16 + t0 * 4 + 1 + ccsel) ^ (g * 4))] = f2tf32(acc[nt][2]);
                Ps[base + ((g * 16 + t1 * 4 + 1 + ccsel) ^ (g * 4))] = f2tf32(acc[nt][3]);
            }
        }
        __syncthreads();

        // ---- PV: O[m16 x 128] += P[m16 x 64] * V[64 x 128] ----
#pragma unroll 2
        for (int ki = 0; ki < 8; ki++) {
            uint4 pa = *(const uint4*)(Ps + warp * 1024 + ki * 128 + aRd);
            uint32_t af[4] = { pa.x, pa.y, pa.z, pa.w };
#pragma unroll
            for (int ni = 0; ni < 16; ni++) {
                uint2 vb = *(const uint2*)(Vs + (ni * 8 + ki) * 68 + bRd);
                uint32_t bf[2] = { vb.x, vb.y };
                mma_tf32(oacc[ni], af, bf);
            }
        }
    }

    // ---- epilogue ----
    const float inv0 = __fdividef(1.f, l0);
    const float inv1 = __fdividef(1.f, l1);
    float* o0 = out + (size_t)qr0 * HID + h * DH;
    float* o1 = out + (size_t)(qr0 + 8) * HID + h * DH;
#pragma unroll
    for (int ni = 0; ni < 16; ni++) {
        int col = ni * 8 + 2 * t;
        *(float2*)(o0 + col) = make_float2(oacc[ni][0] * inv0, oacc[ni][1] * inv0);
        *(float2*)(o1 + col) = make_float2(oacc[ni][2] * inv1, oacc[ni][3] * inv1);
    }
}

// ---------------------------------------------------------------------------
// Inputs (metadata order): hidden_states, cos, sin, attention_mask, wq, wk, wv, wo
// ---------------------------------------------------------------------------
extern "C" void kernel_launch(void* const* d_in, const int* in_sizes, int n_in,
                              void* d_out, int out_size)
{
    const float* hs   = (const float*)d_in[0];
    const float* cosp = (const float*)d_in[1];
    const float* sinp = (const float*)d_in[2];
    const float* wq   = (const float*)d_in[4];
    const float* wk   = (const float*)d_in[5];
    const float* wv   = (const float*)d_in[6];
    const float* wo   = (const float*)d_in[7];
    float* out = (float*)d_out;

    float* qkv = nullptr;
    float* attn = nullptr;
    cudaGetSymbolAddress((void**)&qkv, g_qkv);
    cudaGetSymbolAddress((void**)&attn, g_attn);

    cudaFuncSetAttribute(gemm_mma, cudaFuncAttributeMaxDynamicSharedMemorySize, GEMM_SMEM);
    cudaFuncSetAttribute(attn_mma, cudaFuncAttributeMaxDynamicSharedMemorySize, ATTN_SMEM);

    dim3 blk(256);
    gemm_mma<<<dim3(2048 / 128, S_LEN / 128), blk, GEMM_SMEM>>>(hs, wq, qkv, HID, QKV_LD, 0);
    gemm_mma<<<dim3(512 / 128,  S_LEN / 128), blk, GEMM_SMEM>>>(hs, wk, qkv, HID, QKV_LD, 2048);
    gemm_mma<<<dim3(512 / 128,  S_LEN / 128), blk, GEMM_SMEM>>>(hs, wv, qkv, HID, QKV_LD, 2560);
    rope_kernel<<<S_LEN, 256>>>(qkv, cosp, sinp);
    attn_mma<<<dim3(S_LEN / BM, NH), blk, ATTN_SMEM>>>(qkv, attn);
    gemm_mma<<<dim3(2048 / 128, S_LEN / 128), blk, GEMM_SMEM>>>(attn, wo, out, HID, HID, 0);
}

// round 5
// speedup vs baseline: 3.8223x; 1.5815x over previous
#include <cuda_runtime.h>
#include <cuda_bf16.h>
#include <cstdint>

#define S_LEN   4096
#define HID     2048
#define NH      16
#define NKV     4
#define DH      128
#define QKV_LD  3072
#define Q_SCALE 0.08838834764831845f
#define INV_CAP (1.0f / 50.0f)
#define CAP     50.0f

// Scratch (device globals: no cudaMalloc allowed)
__device__ float g_qkv[(size_t)S_LEN * QKV_LD];   // [S, 3072]: Q(2048) | K(512) | V(512)
__device__ float g_attn[(size_t)S_LEN * HID];     // attention output [S, H*D]

// ===========================================================================
// Helpers
// ===========================================================================
// pack two floats into fp16x2: lo -> low half, hi -> high half (RN)
__device__ __forceinline__ uint32_t pk(float lo, float hi) {
    uint32_t d;
    asm("cvt.rn.f16x2.f32 %0, %1, %2;" : "=r"(d) : "f"(hi), "f"(lo));
    return d;
}

// mma.sync m16n8k16 fp16, f32 accumulate. Word = fp16x2 = one "virtual" k col.
__device__ __forceinline__ void mma_f16(float* c, const uint32_t* a, const uint32_t* b) {
    asm volatile(
        "mma.sync.aligned.m16n8k16.row.col.f32.f16.f16.f32 "
        "{%0,%1,%2,%3}, {%4,%5,%6,%7}, {%8,%9}, {%0,%1,%2,%3};"
        : "+f"(c[0]), "+f"(c[1]), "+f"(c[2]), "+f"(c[3])
        : "r"(a[0]), "r"(a[1]), "r"(a[2]), "r"(a[3]), "r"(b[0]), "r"(b[1]));
}

// Fragment-layout smem word offsets over VIRTUAL k (fp16x2 pairs).
// A block (m16 x vk8) = 128 words: word(g,e,reg) = (g*16+e*4+reg) ^ (g*4)
// B block (vk8 x n8)  = 64 words + 4 skew: ((g*4+e)*2+reg) ^ ((g&4)>>1)
__device__ __forceinline__ int aw(int g, int e, int reg) {
    return ((g * 16 + e * 4 + reg) ^ (g * 4));
}
__device__ __forceinline__ int bw(int g, int e, int reg) {
    return (((g * 4 + e) * 2 + reg) ^ ((g & 4) >> 1));
}

// ===========================================================================
// FP16 mma.sync GEMM: C[m, n] = sum_k A[m,k]*B[n,k]
// Tile 128x128, k-chunk 32 floats (= 2 virtual k8 steps). 8 warps (2m x 4n).
// B selected per n-tile: [0,2048)->B0, [2048,2560)->B1, [2560,3072)->B2.
// ===========================================================================
#define A_WORDS 2048            // 8 mi * 2 ki * 128
#define B_WORDS 2176            // 16 ni * 2 ki * 68
#define GEMM_SMEM ((2 * A_WORDS + 2 * B_WORDS) * 4)

__global__ __launch_bounds__(256) void gemm_f16(
    const float* __restrict__ A, const float* __restrict__ B0,
    const float* __restrict__ B1, const float* __restrict__ B2,
    float* __restrict__ C, int Kd, int ldc)
{
    extern __shared__ uint32_t smw[];
    uint32_t* Asm[2] = { smw, smw + A_WORDS };
    uint32_t* Bsm[2] = { smw + 2 * A_WORDS, smw + 2 * A_WORDS + B_WORDS };

    const int tid  = threadIdx.x;
    const int lane = tid & 31;
    const int warp = tid >> 5;
    const int wm   = warp >> 2;
    const int wn   = warp & 3;
    const int bm   = blockIdx.y * 128;
    const int bnG  = blockIdx.x * 128;
    const int NC   = Kd / 32;

    const float* Bp; int bloc;
    if (bnG < 2048)      { Bp = B0; bloc = bnG; }
    else if (bnG < 2560) { Bp = B1; bloc = bnG - 2048; }
    else                 { Bp = B2; bloc = bnG - 2560; }

    const int r  = tid >> 2;
    const int c4 = tid & 3;
    const float* pA = A  + (size_t)(bm + r)   * Kd + c4 * 4;
    const float* pB = Bp + (size_t)(bloc + r) * Kd + c4 * 4;

    int aMi[2], aG[2], regA[2], bNi[2], bG[2];
    const int cH = c4 >> 1;               // ccSel / regB
    const int e0 = (c4 & 1) * 2;
#pragma unroll
    for (int rs = 0; rs < 2; rs++) {
        int R = r + 64 * rs;
        aMi[rs] = R >> 4;
        aG[rs]  = R & 7;
        regA[rs] = ((R & 15) >> 3) + 2 * cH;
        bNi[rs] = R >> 3; bG[rs] = R & 7;
    }

    float acc[4][4][4];
#pragma unroll
    for (int i = 0; i < 4; i++)
#pragma unroll
        for (int j = 0; j < 4; j++)
#pragma unroll
            for (int e = 0; e < 4; e++) acc[i][j][e] = 0.f;

    const int g = lane >> 2, t = lane & 3;
    const int aRd = (g * 16 + t * 4) ^ (g * 4);
    const int bRd = (lane * 2) ^ ((g & 4) >> 1);

    float4 ra[4], rb[4];

    // -------- prologue: chunk 0 --------
#pragma unroll
    for (int rs = 0; rs < 2; rs++)
#pragma unroll
        for (int cs = 0; cs < 2; cs++) {
            ra[rs * 2 + cs] = *(const float4*)(pA + (size_t)rs * 64 * Kd + cs * 16);
            rb[rs * 2 + cs] = *(const float4*)(pB + (size_t)rs * 64 * Kd + cs * 16);
        }
#pragma unroll
    for (int rs = 0; rs < 2; rs++)
#pragma unroll
        for (int cs = 0; cs < 2; cs++) {
            const float4 va = ra[rs * 2 + cs];
            const float4 vb = rb[rs * 2 + cs];
            uint32_t* Ad = Asm[0] + aMi[rs] * 256 + cs * 128;
            uint32_t* Bd = Bsm[0] + (bNi[rs] * 2 + cs) * 68;
            Ad[aw(aG[rs], e0,     regA[rs])] = pk(va.x, va.y);
            Ad[aw(aG[rs], e0 + 1, regA[rs])] = pk(va.z, va.w);
            Bd[bw(bG[rs], e0,     cH)]       = pk(vb.x, vb.y);
            Bd[bw(bG[rs], e0 + 1, cH)]       = pk(vb.z, vb.w);
        }
    __syncthreads();

    // -------- main loop --------
    for (int ic = 0; ic < NC; ic++) {
        const bool nb = (ic + 1 < NC);
        if (nb) {
            const size_t ko = (size_t)(ic + 1) * 32;
#pragma unroll
            for (int rs = 0; rs < 2; rs++)
#pragma unroll
                for (int cs = 0; cs < 2; cs++) {
                    ra[rs * 2 + cs] = *(const float4*)(pA + (size_t)rs * 64 * Kd + cs * 16 + ko);
                    rb[rs * 2 + cs] = *(const float4*)(pB + (size_t)rs * 64 * Kd + cs * 16 + ko);
                }
        }

        const uint32_t* Ab = Asm[ic & 1];
        const uint32_t* Bb = Bsm[ic & 1];
#pragma unroll
        for (int ki = 0; ki < 2; ki++) {
            uint32_t af[4][4], bf[4][2];
#pragma unroll
            for (int mi = 0; mi < 4; mi++) {
                uint4 q = *(const uint4*)(Ab + (wm * 4 + mi) * 256 + ki * 128 + aRd);
                af[mi][0] = q.x; af[mi][1] = q.y; af[mi][2] = q.z; af[mi][3] = q.w;
            }
#pragma unroll
            for (int ni = 0; ni < 4; ni++) {
                uint2 q = *(const uint2*)(Bb + ((wn * 4 + ni) * 2 + ki) * 68 + bRd);
                bf[ni][0] = q.x; bf[ni][1] = q.y;
            }
#pragma unroll
            for (int mi = 0; mi < 4; mi++)
#pragma unroll
                for (int ni = 0; ni < 4; ni++)
                    mma_f16(acc[mi][ni], af[mi], bf[ni]);
        }

        if (nb) {
            uint32_t* Aw2 = Asm[(ic + 1) & 1];
            uint32_t* Bw2 = Bsm[(ic + 1) & 1];
#pragma unroll
            for (int rs = 0; rs < 2; rs++)
#pragma unroll
                for (int cs = 0; cs < 2; cs++) {
                    const float4 va = ra[rs * 2 + cs];
                    const float4 vb = rb[rs * 2 + cs];
                    uint32_t* Ad = Aw2 + aMi[rs] * 256 + cs * 128;
                    uint32_t* Bd = Bw2 + (bNi[rs] * 2 + cs) * 68;
                    Ad[aw(aG[rs], e0,     regA[rs])] = pk(va.x, va.y);
                    Ad[aw(aG[rs], e0 + 1, regA[rs])] = pk(va.z, va.w);
                    Bd[bw(bG[rs], e0,     cH)]       = pk(vb.x, vb.y);
                    Bd[bw(bG[rs], e0 + 1, cH)]       = pk(vb.z, vb.w);
                }
            __syncthreads();
        }
    }

    // -------- epilogue --------
#pragma unroll
    for (int mi = 0; mi < 4; mi++)
#pragma unroll
        for (int ni = 0; ni < 4; ni++) {
            const int row = bm + wm * 64 + mi * 16 + g;
            const int col = bnG + wn * 32 + ni * 8 + t * 2;
            float* p0 = C + (size_t)row * ldc + col;
            float* p1 = C + (size_t)(row + 8) * ldc + col;
            *(float2*)p0 = make_float2(acc[mi][ni][0], acc[mi][ni][1]);
            *(float2*)p1 = make_float2(acc[mi][ni][2], acc[mi][ni][3]);
        }
}

// ---------------------------------------------------------------------------
// RoPE (in place on g_qkv) + scale Q.
// ---------------------------------------------------------------------------
__global__ void rope_kernel(float* __restrict__ qkv,
                            const float* __restrict__ cosp,
                            const float* __restrict__ sinp)
{
    const int s = blockIdx.x;
    const float* c  = cosp + (size_t)s * DH;
    const float* sn = sinp + (size_t)s * DH;
    float* row = qkv + (size_t)s * QKV_LD;
    for (int i = threadIdx.x; i < 20 * 64; i += blockDim.x) {
        int hh = i >> 6;
        int d  = i & 63;
        int base = (hh < 16) ? hh * 128 : (2048 + (hh - 16) * 128);
        float x1 = row[base + d];
        float x2 = row[base + d + 64];
        float y1 = x1 * c[d]      - x2 * sn[d];
        float y2 = x2 * c[d + 64] + x1 * sn[d + 64];
        if (hh < 16) { y1 *= Q_SCALE; y2 *= Q_SCALE; }
        row[base + d]      = y1;
        row[base + d + 64] = y2;
    }
}

// ===========================================================================
// Flash attention with fp16 mma.sync. BM=128 q rows, BN=64 keys, 8 warps.
// Same virtual-pair fragment layouts. Warp-local softmax.
// ===========================================================================
#define BM 128
#define BN 64
#define AQ_OFF 0                        // Q: 8 mi * 8 ki * 128 = 8192 words
#define AK_OFF 8192                     // K: 8 nI * 8 ki * 68 = 4352
#define AV_OFF (8192 + 4352)            // V^T: 16 ni * 4 ki * 68 = 4352
#define AP_OFF (8192 + 2 * 4352)        // P: 8 warps * 4 ki * 128 = 4096
#define ATTN_WORDS (8192 + 2 * 4352 + 4096)
#define ATTN_SMEM (ATTN_WORDS * 4)

__global__ __launch_bounds__(256) void attn_mma(
    const float* __restrict__ qkv, float* __restrict__ out)
{
    extern __shared__ uint32_t sw[];
    uint32_t* Qs = sw + AQ_OFF;
    uint32_t* Ks = sw + AK_OFF;
    uint32_t* Vs = sw + AV_OFF;
    uint32_t* Ps = sw + AP_OFF;

    const int tid  = threadIdx.x;
    const int lane = tid & 31;
    const int warp = tid >> 5;
    const int qb   = (int)gridDim.x - 1 - (int)blockIdx.x;  // big tiles first
    const int h    = blockIdx.y;
    const int kvg  = h >> 2;

    const int g = lane >> 2, t = lane & 3;
    const int aRd = (g * 16 + t * 4) ^ (g * 4);
    const int bRd = (lane * 2) ^ ((g & 4) >> 1);

    const float* Qg = qkv + h * DH;
    const float* Kg = qkv + 2048 + kvg * DH;
    const float* Vg = qkv + 2560 + kvg * DH;

    // ---- Q tile -> A-frag layout (persistent) ----
    for (int i = tid; i < BM * 32; i += 256) {
        int r = i >> 5, c4 = i & 31;
        float4 v = *(const float4*)(Qg + (size_t)(qb * BM + r) * QKV_LD + c4 * 4);
        int mi = r >> 4, rr = r & 15, hi = rr >> 3, gg = rr & 7;
        int ki = c4 >> 2;
        int reg = hi + 2 * ((c4 & 3) >> 1);
        int e0  = (c4 & 1) * 2;
        uint32_t* Qd = Qs + mi * 1024 + ki * 128;
        Qd[aw(gg, e0,     reg)] = pk(v.x, v.y);
        Qd[aw(gg, e0 + 1, reg)] = pk(v.z, v.w);
    }

    float oacc[16][4];
#pragma unroll
    for (int i = 0; i < 16; i++)
#pragma unroll
        for (int e = 0; e < 4; e++) oacc[i][e] = 0.f;
    float m0 = -1e30f, m1 = -1e30f, l0 = 0.f, l1 = 0.f;

    const int qr0 = qb * BM + warp * 16 + g;   // row of c0,c1
    const int ntiles = 2 * qb + 2;

    for (int kt = 0; kt < ntiles; kt++) {
        __syncthreads();
        // ---- K tile -> B-frag layout ----
        for (int i = tid; i < BN * 32; i += 256) {
            int r = i >> 5, c4 = i & 31;
            float4 v = *(const float4*)(Kg + (size_t)(kt * BN + r) * QKV_LD + c4 * 4);
            int nI = r >> 3, gg = r & 7;
            int ki = c4 >> 2;
            int reg = (c4 & 3) >> 1;
            int e0  = (c4 & 1) * 2;
            uint32_t* Kd = Ks + (nI * 8 + ki) * 68;
            Kd[bw(gg, e0,     reg)] = pk(v.x, v.y);
            Kd[bw(gg, e0 + 1, reg)] = pk(v.z, v.w);
        }
        // ---- V tile (transposed pairs) -> B-frag layout: n=dim, vk=key pair ----
        for (int i = tid; i < 32 * 32; i += 256) {
            int kp = i >> 5, c4 = i & 31;     // key pair, dim float4
            const float* v0p = Vg + (size_t)(kt * BN + 2 * kp) * QKV_LD + c4 * 4;
            float4 v0 = *(const float4*)v0p;
            float4 v1 = *(const float4*)(v0p + QKV_LD);
            int ki = kp >> 3, kc = kp & 7;
            int reg = kc >> 2, e = kc & 3;
            float a0[4] = { v0.x, v0.y, v0.z, v0.w };
            float a1[4] = { v1.x, v1.y, v1.z, v1.w };
#pragma unroll
            for (int j = 0; j < 4; j++) {
                int d = c4 * 4 + j;
                int ni = d >> 3, gg = d & 7;
                Vs[(ni * 4 + ki) * 68 + bw(gg, e, reg)] = pk(a0[j], a1[j]);
            }
        }
        __syncthreads();

        // ---- QK: S[m16 x 64] per warp ----
        float acc[8][4];
#pragma unroll
        for (int nt = 0; nt < 8; nt++)
#pragma unroll
            for (int e = 0; e < 4; e++) acc[nt][e] = 0.f;
#pragma unroll 4
        for (int ki = 0; ki < 8; ki++) {
            uint4 qa = *(const uint4*)(Qs + warp * 1024 + ki * 128 + aRd);
            uint32_t af[4] = { qa.x, qa.y, qa.z, qa.w };
#pragma unroll
            for (int nt = 0; nt < 8; nt++) {
                uint2 kb = *(const uint2*)(Ks + (nt * 8 + ki) * 68 + bRd);
                uint32_t bf[2] = { kb.x, kb.y };
                mma_f16(acc[nt], af, bf);
            }
        }

        // ---- softcap + causal mask ----
        const bool diag = (kt >= 2 * qb);
        float mt0 = -1e30f, mt1 = -1e30f;
#pragma unroll
        for (int nt = 0; nt < 8; nt++) {
#pragma unroll
            for (int e = 0; e < 4; e++) {
                float x = acc[nt][e] * INV_CAP;
                x = fminf(fmaxf(x, -20.f), 20.f);
                float ex = __expf(2.f * x);
                float v = __fdividef(ex - 1.f, ex + 1.f) * CAP;
                if (diag) {
                    int kc = kt * BN + nt * 8 + 2 * t + (e & 1);
                    int qr = qr0 + ((e >> 1) << 3);
                    if (kc > qr) v = -1e30f;
                }
                acc[nt][e] = v;
                if (e < 2) mt0 = fmaxf(mt0, v); else mt1 = fmaxf(mt1, v);
            }
        }
        mt0 = fmaxf(mt0, __shfl_xor_sync(0xffffffffu, mt0, 1));
        mt0 = fmaxf(mt0, __shfl_xor_sync(0xffffffffu, mt0, 2));
        mt1 = fmaxf(mt1, __shfl_xor_sync(0xffffffffu, mt1, 1));
        mt1 = fmaxf(mt1, __shfl_xor_sync(0xffffffffu, mt1, 2));

        const float mn0 = fmaxf(m0, mt0), mn1 = fmaxf(m1, mt1);
        const float al0 = __expf(m0 - mn0), al1 = __expf(m1 - mn1);
        m0 = mn0; m1 = mn1;

        float rs0 = 0.f, rs1 = 0.f;
#pragma unroll
        for (int nt = 0; nt < 8; nt++) {
            acc[nt][0] = __expf(acc[nt][0] - mn0);
            acc[nt][1] = __expf(acc[nt][1] - mn0);
            acc[nt][2] = __expf(acc[nt][2] - mn1);
            acc[nt][3] = __expf(acc[nt][3] - mn1);
            rs0 += acc[nt][0] + acc[nt][1];
            rs1 += acc[nt][2] + acc[nt][3];
        }
        rs0 += __shfl_xor_sync(0xffffffffu, rs0, 1);
        rs0 += __shfl_xor_sync(0xffffffffu, rs0, 2);
        rs1 += __shfl_xor_sync(0xffffffffu, rs1, 1);
        rs1 += __shfl_xor_sync(0xffffffffu, rs1, 2);
        l0 = l0 * al0 + rs0;
        l1 = l1 * al1 + rs1;

#pragma unroll
        for (int ni = 0; ni < 16; ni++) {
            oacc[ni][0] *= al0; oacc[ni][1] *= al0;
            oacc[ni][2] *= al1; oacc[ni][3] *= al1;
        }

        // ---- P (C-frag) -> smem in A-frag layout (warp-private) ----
#pragma unroll
        for (int nt = 0; nt < 8; nt++) {
            int ki = nt >> 1;
            int reg0 = 2 * (nt & 1);
            uint32_t* Pd = Ps + warp * 512 + ki * 128;
            Pd[aw(g, t, reg0)]     = pk(acc[nt][0], acc[nt][1]);
            Pd[aw(g, t, reg0 + 1)] = pk(acc[nt][2], acc[nt][3]);
        }
        __syncwarp();

        // ---- PV: O[m16 x 128] += P[m16 x 64] * V[64 x 128] ----
#pragma unroll 2
        for (int ki = 0; ki < 4; ki++) {
            uint4 pa = *(const uint4*)(Ps + warp * 512 + ki * 128 + aRd);
            uint32_t af[4] = { pa.x, pa.y, pa.z, pa.w };
#pragma unroll
            for (int ni = 0; ni < 16; ni++) {
                uint2 vb = *(const uint2*)(Vs + (ni * 4 + ki) * 68 + bRd);
                uint32_t bf[2] = { vb.x, vb.y };
                mma_f16(oacc[ni], af, bf);
            }
        }
    }

    // ---- epilogue ----
    const float inv0 = __fdividef(1.f, l0);
    const float inv1 = __fdividef(1.f, l1);
    float* o0 = out + (size_t)qr0 * HID + h * DH;
    float* o1 = out + (size_t)(qr0 + 8) * HID + h * DH;
#pragma unroll
    for (int ni = 0; ni < 16; ni++) {
        int col = ni * 8 + 2 * t;
        *(float2*)(o0 + col) = make_float2(oacc[ni][0] * inv0, oacc[ni][1] * inv0);
        *(float2*)(o1 + col) = make_float2(oacc[ni][2] * inv1, oacc[ni][3] * inv1);
    }
}

// ---------------------------------------------------------------------------
// Inputs (metadata order): hidden_states, cos, sin, attention_mask, wq, wk, wv, wo
// ---------------------------------------------------------------------------
extern "C" void kernel_launch(void* const* d_in, const int* in_sizes, int n_in,
                              void* d_out, int out_size)
{
    const float* hs   = (const float*)d_in[0];
    const float* cosp = (const float*)d_in[1];
    const float* sinp = (const float*)d_in[2];
    const float* wq   = (const float*)d_in[4];
    const float* wk   = (const float*)d_in[5];
    const float* wv   = (const float*)d_in[6];
    const float* wo   = (const float*)d_in[7];
    float* out = (float*)d_out;

    float* qkv = nullptr;
    float* attn = nullptr;
    cudaGetSymbolAddress((void**)&qkv, g_qkv);
    cudaGetSymbolAddress((void**)&attn, g_attn);

    cudaFuncSetAttribute(gemm_f16, cudaFuncAttributeMaxDynamicSharedMemorySize, GEMM_SMEM);
    cudaFuncSetAttribute(attn_mma, cudaFuncAttributeMaxDynamicSharedMemorySize, ATTN_SMEM);

    dim3 blk(256);
    // Fused QKV projection: one launch, 24x32 CTAs, writes [S, 3072]
    gemm_f16<<<dim3(3072 / 128, S_LEN / 128), blk, GEMM_SMEM>>>(hs, wq, wk, wv, qkv, HID, QKV_LD);
    rope_kernel<<<S_LEN, 256>>>(qkv, cosp, sinp);
    attn_mma<<<dim3(S_LEN / BM, NH), blk, ATTN_SMEM>>>(qkv, attn);
    // Output projection
    gemm_f16<<<dim3(2048 / 128, S_LEN / 128), blk, GEMM_SMEM>>>(attn, wo, wo, wo, out, HID, HID);
}

// round 6
// speedup vs baseline: 4.1642x; 1.0895x over previous
#include <cuda_runtime.h>
#include <cuda_bf16.h>
#include <cstdint>

#define S_LEN   4096
#define HID     2048
#define NH      16
#define NKV     4
#define DH      128
#define QKV_LD  3072
#define QK16_LD 1280
#define Q_SCALE 0.08838834764831845f
#define INV_CAP (1.0f / 50.0f)
#define CAP     50.0f

// Scratch (device globals: no cudaMalloc allowed)
__device__ float    g_qkv[(size_t)S_LEN * QKV_LD];    // [S,3072]: Q | K | V (f32)
__device__ uint32_t g_qk16[(size_t)S_LEN * QK16_LD];  // [S,1280]: Q(1024w) | K(256w) fp16x2 dim-pairs
__device__ float    g_attn[(size_t)S_LEN * HID];      // attention output [S, H*D]

// ===========================================================================
// Helpers
// ===========================================================================
__device__ __forceinline__ uint32_t pk(float lo, float hi) {
    uint32_t d;
    asm("cvt.rn.f16x2.f32 %0, %1, %2;" : "=r"(d) : "f"(hi), "f"(lo));
    return d;
}
__device__ __forceinline__ void mma_f16(float* c, const uint32_t* a, const uint32_t* b) {
    asm volatile(
        "mma.sync.aligned.m16n8k16.row.col.f32.f16.f16.f32 "
        "{%0,%1,%2,%3}, {%4,%5,%6,%7}, {%8,%9}, {%0,%1,%2,%3};"
        : "+f"(c[0]), "+f"(c[1]), "+f"(c[2]), "+f"(c[3])
        : "r"(a[0]), "r"(a[1]), "r"(a[2]), "r"(a[3]), "r"(b[0]), "r"(b[1]));
}
// Fragment-layout word offsets over virtual k (fp16x2 pairs).
__device__ __forceinline__ int aw(int g, int e, int reg) {
    return ((g * 16 + e * 4 + reg) ^ (g * 4));
}
__device__ __forceinline__ int bw(int g, int e, int reg) {
    return (((g * 4 + e) * 2 + reg) ^ ((g & 4) >> 1));
}

// ===========================================================================
// FP16 mma.sync GEMM: C[m,n] = sum_k A[m,k]*B[n,k]. Tile 128x64, kc=32 floats.
// 8 warps (4m x 2n), 32 C-regs/thread -> 2 CTAs/SM.
// ===========================================================================
#define A2_WORDS 2048            // 8 mi * 2 ki * 128
#define B2_WORDS 1088            // 8 nI * 2 ki * 68
#define GEMM_SMEM ((2 * A2_WORDS + 2 * B2_WORDS) * 4)

__global__ __launch_bounds__(256, 2) void gemm_f16(
    const float* __restrict__ A, const float* __restrict__ B0,
    const float* __restrict__ B1, const float* __restrict__ B2,
    float* __restrict__ C, int Kd, int ldc)
{
    extern __shared__ uint32_t smw[];
    uint32_t* Asm[2] = { smw, smw + A2_WORDS };
    uint32_t* Bsm[2] = { smw + 2 * A2_WORDS, smw + 2 * A2_WORDS + B2_WORDS };

    const int tid  = threadIdx.x;
    const int lane = tid & 31;
    const int warp = tid >> 5;
    const int wm   = warp >> 1;          // 0..3
    const int wn   = warp & 1;           // 0..1
    const int bm   = blockIdx.y * 128;
    const int bnG  = blockIdx.x * 64;
    const int NC   = Kd / 32;

    const float* Bp; int bloc;
    if (bnG < 2048)      { Bp = B0; bloc = bnG; }
    else if (bnG < 2560) { Bp = B1; bloc = bnG - 2048; }
    else                 { Bp = B2; bloc = bnG - 2560; }

    const int r  = tid >> 2;             // 0..63
    const int c4 = tid & 3;
    const float* pA = A  + (size_t)(bm + r)    * Kd + c4 * 4;
    const float* pB = Bp + (size_t)(bloc + r)  * Kd + c4 * 4;

    const int cH = c4 >> 1;
    const int e0 = (c4 & 1) * 2;
    int aMi[2], aG[2], regA[2];
#pragma unroll
    for (int rs = 0; rs < 2; rs++) {
        int R = r + 64 * rs;
        aMi[rs] = R >> 4; aG[rs] = R & 7;
        regA[rs] = ((R & 15) >> 3) + 2 * cH;
    }
    const int bNi = r >> 3, bG = r & 7;

    float acc[2][4][4];
#pragma unroll
    for (int i = 0; i < 2; i++)
#pragma unroll
        for (int j = 0; j < 4; j++)
#pragma unroll
            for (int e = 0; e < 4; e++) acc[i][j][e] = 0.f;

    const int g = lane >> 2, t = lane & 3;
    const int aRd = (g * 16 + t * 4) ^ (g * 4);
    const int bRd = (lane * 2) ^ ((g & 4) >> 1);

    float4 ra[4], rb[2];

    // -------- prologue: chunk 0 --------
#pragma unroll
    for (int rs = 0; rs < 2; rs++)
#pragma unroll
        for (int cs = 0; cs < 2; cs++)
            ra[rs * 2 + cs] = *(const float4*)(pA + (size_t)rs * 64 * Kd + cs * 16);
#pragma unroll
    for (int cs = 0; cs < 2; cs++)
        rb[cs] = *(const float4*)(pB + cs * 16);
#pragma unroll
    for (int rs = 0; rs < 2; rs++)
#pragma unroll
        for (int cs = 0; cs < 2; cs++) {
            const float4 va = ra[rs * 2 + cs];
            uint32_t* Ad = Asm[0] + aMi[rs] * 256 + cs * 128;
            Ad[aw(aG[rs], e0,     regA[rs])] = pk(va.x, va.y);
            Ad[aw(aG[rs], e0 + 1, regA[rs])] = pk(va.z, va.w);
        }
#pragma unroll
    for (int cs = 0; cs < 2; cs++) {
        const float4 vb = rb[cs];
        uint32_t* Bd = Bsm[0] + (bNi * 2 + cs) * 68;
        Bd[bw(bG, e0,     cH)] = pk(vb.x, vb.y);
        Bd[bw(bG, e0 + 1, cH)] = pk(vb.z, vb.w);
    }
    __syncthreads();

    // -------- main loop --------
    for (int ic = 0; ic < NC; ic++) {
        const bool nb = (ic + 1 < NC);
        if (nb) {
            const size_t ko = (size_t)(ic + 1) * 32;
#pragma unroll
            for (int rs = 0; rs < 2; rs++)
#pragma unroll
                for (int cs = 0; cs < 2; cs++)
                    ra[rs * 2 + cs] = *(const float4*)(pA + (size_t)rs * 64 * Kd + cs * 16 + ko);
#pragma unroll
            for (int cs = 0; cs < 2; cs++)
                rb[cs] = *(const float4*)(pB + cs * 16 + ko);
        }

        const uint32_t* Ab = Asm[ic & 1];
        const uint32_t* Bb = Bsm[ic & 1];
#pragma unroll
        for (int ki = 0; ki < 2; ki++) {
            uint32_t af[2][4], bf[4][2];
#pragma unroll
            for (int mi = 0; mi < 2; mi++) {
                uint4 q = *(const uint4*)(Ab + (wm * 2 + mi) * 256 + ki * 128 + aRd);
                af[mi][0] = q.x; af[mi][1] = q.y; af[mi][2] = q.z; af[mi][3] = q.w;
            }
#pragma unroll
            for (int ni = 0; ni < 4; ni++) {
                uint2 q = *(const uint2*)(Bb + ((wn * 4 + ni) * 2 + ki) * 68 + bRd);
                bf[ni][0] = q.x; bf[ni][1] = q.y;
            }
#pragma unroll
            for (int mi = 0; mi < 2; mi++)
#pragma unroll
                for (int ni = 0; ni < 4; ni++)
                    mma_f16(acc[mi][ni], af[mi], bf[ni]);
        }

        if (nb) {
            uint32_t* Aw2 = Asm[(ic + 1) & 1];
            uint32_t* Bw2 = Bsm[(ic + 1) & 1];
#pragma unroll
            for (int rs = 0; rs < 2; rs++)
#pragma unroll
                for (int cs = 0; cs < 2; cs++) {
                    const float4 va = ra[rs * 2 + cs];
                    uint32_t* Ad = Aw2 + aMi[rs] * 256 + cs * 128;
                    Ad[aw(aG[rs], e0,     regA[rs])] = pk(va.x, va.y);
                    Ad[aw(aG[rs], e0 + 1, regA[rs])] = pk(va.z, va.w);
                }
#pragma unroll
            for (int cs = 0; cs < 2; cs++) {
                const float4 vb = rb[cs];
                uint32_t* Bd = Bw2 + (bNi * 2 + cs) * 68;
                Bd[bw(bG, e0,     cH)] = pk(vb.x, vb.y);
                Bd[bw(bG, e0 + 1, cH)] = pk(vb.z, vb.w);
            }
            __syncthreads();
        }
    }

    // -------- epilogue --------
#pragma unroll
    for (int mi = 0; mi < 2; mi++)
#pragma unroll
        for (int ni = 0; ni < 4; ni++) {
            const int row = bm + wm * 32 + mi * 16 + g;
            const int col = bnG + wn * 32 + ni * 8 + t * 2;
            float* p0 = C + (size_t)row * ldc + col;
            float* p1 = C + (size_t)(row + 8) * ldc + col;
            *(float2*)p0 = make_float2(acc[mi][ni][0], acc[mi][ni][1]);
            *(float2*)p1 = make_float2(acc[mi][ni][2], acc[mi][ni][3]);
        }
}

// ---------------------------------------------------------------------------
// RoPE + Q scale, output packed fp16x2 dim-pairs: [S][1280]: Q(1024w) | K(256w)
// ---------------------------------------------------------------------------
__global__ void rope_pack(const float* __restrict__ qkv, uint32_t* __restrict__ qk16,
                          const float* __restrict__ cosp, const float* __restrict__ sinp)
{
    const int s = blockIdx.x;
    const float* c  = cosp + (size_t)s * DH;
    const float* sn = sinp + (size_t)s * DH;
    const float* row = qkv + (size_t)s * QKV_LD;
    uint32_t* orow = qk16 + (size_t)s * QK16_LD;
    for (int i = threadIdx.x; i < 20 * 32; i += blockDim.x) {
        int hh = i >> 5;
        int c0 = i & 31;              // vcol within first half
        int d0 = 2 * c0;
        int base = (hh < 16) ? hh * 128 : (2048 + (hh - 16) * 128);
        float x1a = row[base + d0],      x1b = row[base + d0 + 1];
        float x2a = row[base + d0 + 64], x2b = row[base + d0 + 65];
        float y1a = x1a * c[d0]      - x2a * sn[d0];
        float y1b = x1b * c[d0 + 1]  - x2b * sn[d0 + 1];
        float y2a = x2a * c[d0 + 64] + x1a * sn[d0 + 64];
        float y2b = x2b * c[d0 + 65] + x1b * sn[d0 + 65];
        if (hh < 16) { y1a *= Q_SCALE; y1b *= Q_SCALE; y2a *= Q_SCALE; y2b *= Q_SCALE; }
        int obase = (hh < 16) ? hh * 64 : (1024 + (hh - 16) * 64);
        orow[obase + c0]      = pk(y1a, y1b);
        orow[obase + 32 + c0] = pk(y2a, y2b);
    }
}

// ===========================================================================
// Flash attention, fp16 mma.sync. BM=128, BN=64, 8 warps, warp-local softmax.
// Q/K from packed fp16 buffer; K/V double-buffered smem with reg prefetch.
// ===========================================================================
#define BM 128
#define BN 64
#define AQ_OFF 0                        // Q: 8192 words
#define AK_OFF 8192                     // K bufs: 2 x 4352
#define AV_OFF (8192 + 2 * 4352)        // V bufs: 2 x 4352
#define AP_OFF (8192 + 4 * 4352)        // P: 4096
#define ATTN_WORDS (8192 + 4 * 4352 + 4096)
#define ATTN_SMEM (ATTN_WORDS * 4)

__global__ __launch_bounds__(256, 1) void attn_mma(
    const uint32_t* __restrict__ qk16, const float* __restrict__ qkv,
    float* __restrict__ out)
{
    extern __shared__ uint32_t sw[];
    uint32_t* Qs = sw + AQ_OFF;
    uint32_t* Kb[2] = { sw + AK_OFF, sw + AK_OFF + 4352 };
    uint32_t* Vb[2] = { sw + AV_OFF, sw + AV_OFF + 4352 };
    uint32_t* Ps = sw + AP_OFF;

    const int tid  = threadIdx.x;
    const int lane = tid & 31;
    const int warp = tid >> 5;
    const int qb   = (int)gridDim.x - 1 - (int)blockIdx.x;  // big tiles first
    const int h    = blockIdx.y;
    const int kvg  = h >> 2;

    const int g = lane >> 2, t = lane & 3;
    const int aRd = (g * 16 + t * 4) ^ (g * 4);
    const int bRd = (lane * 2) ^ ((g & 4) >> 1);

    const uint32_t* Qg = qk16 + h * 64;
    const uint32_t* Kg = qk16 + 1024 + kvg * 64;
    const float*    Vg = qkv + 2560 + kvg * DH;

    // ---- Q tile -> A-frag layout (fp16 words, address permute only) ----
    for (int i = tid; i < BM * 16; i += 256) {
        int r = i >> 4, u = i & 15;
        uint4 U = *(const uint4*)(Qg + (size_t)(qb * BM + r) * QK16_LD + u * 4);
        int mi = r >> 4, rr = r & 15, hi = rr >> 3, gg = rr & 7;
        uint32_t* Qd = Qs + mi * 1024;
        uint32_t W[4] = { U.x, U.y, U.z, U.w };
#pragma unroll
        for (int j = 0; j < 4; j++) {
            int v = 4 * u + j;
            Qd[(v >> 3) * 128 + aw(gg, v & 3, hi + 2 * ((v >> 2) & 1))] = W[j];
        }
    }

    // K/V loader geometry
    const int kr_r = tid >> 2, kr_u4 = (tid & 3) << 2;   // K: 4 iters of (r += 64? no: below)
    (void)kr_r; (void)kr_u4;

    // ---- prologue: load tile 0 into buffers 0 ----
    {
        for (int i = tid; i < BN * 16; i += 256) {
            int r = i >> 4, u = i & 15;
            uint4 U = *(const uint4*)(Kg + (size_t)r * QK16_LD + u * 4);
            int nI = r >> 3, gg = r & 7;
            uint32_t W[4] = { U.x, U.y, U.z, U.w };
#pragma unroll
            for (int j = 0; j < 4; j++) {
                int v = 4 * u + j;
                Kb[0][(nI * 8 + (v >> 3)) * 68 + bw(gg, v & 3, (v >> 2) & 1)] = W[j];
            }
        }
        for (int i = tid; i < 32 * 32; i += 256) {
            int kp = i >> 5, c4 = i & 31;
            const float* v0p = Vg + (size_t)(2 * kp) * QKV_LD + c4 * 4;
            float4 v0 = *(const float4*)v0p;
            float4 v1 = *(const float4*)(v0p + QKV_LD);
            int ki = kp >> 3, kc = kp & 7;
            int reg = kc >> 2, e = kc & 3;
            float a0[4] = { v0.x, v0.y, v0.z, v0.w };
            float a1[4] = { v1.x, v1.y, v1.z, v1.w };
#pragma unroll
            for (int j = 0; j < 4; j++) {
                int d = c4 * 4 + j;
                Vb[0][((d >> 3) * 4 + ki) * 68 + bw(d & 7, e, reg)] = pk(a0[j], a1[j]);
            }
        }
    }
    __syncthreads();

    float oacc[16][4];
#pragma unroll
    for (int i = 0; i < 16; i++)
#pragma unroll
        for (int e = 0; e < 4; e++) oacc[i][e] = 0.f;
    float m0 = -1e30f, m1 = -1e30f, l0 = 0.f, l1 = 0.f;

    const int qr0 = qb * BM + warp * 16 + g;
    const int ntiles = 2 * qb + 2;

    for (int kt = 0; kt < ntiles; kt++) {
        const bool pf = (kt + 1 < ntiles);
        const uint32_t* Kc = Kb[kt & 1];
        const uint32_t* Vc = Vb[kt & 1];
        uint32_t* Kn = Kb[(kt + 1) & 1];
        uint32_t* Vn = Vb[(kt + 1) & 1];

        // ---- prefetch K(kt+1) into regs (latency hides behind QK) ----
        uint4 kr[4];
        if (pf) {
#pragma unroll
            for (int ii = 0; ii < 4; ii++) {
                int idx = tid + ii * 256;
                int r = idx >> 4, u = idx & 15;
                kr[ii] = *(const uint4*)(Kg + (size_t)((kt + 1) * BN + r) * QK16_LD + u * 4);
            }
        }

        // ---- QK ----
        float acc[8][4];
#pragma unroll
        for (int nt = 0; nt < 8; nt++)
#pragma unroll
            for (int e = 0; e < 4; e++) acc[nt][e] = 0.f;
#pragma unroll 4
        for (int ki = 0; ki < 8; ki++) {
            uint4 qa = *(const uint4*)(Qs + warp * 1024 + ki * 128 + aRd);
            uint32_t af[4] = { qa.x, qa.y, qa.z, qa.w };
#pragma unroll
            for (int nt = 0; nt < 8; nt++) {
                uint2 kb2 = *(const uint2*)(Kc + (nt * 8 + ki) * 68 + bRd);
                uint32_t bf[2] = { kb2.x, kb2.y };
                mma_f16(acc[nt], af, bf);
            }
        }

        // ---- softcap + causal ----
        const bool diag = (kt >= 2 * qb);
        float mt0 = -1e30f, mt1 = -1e30f;
#pragma unroll
        for (int nt = 0; nt < 8; nt++) {
#pragma unroll
            for (int e = 0; e < 4; e++) {
                float x = acc[nt][e] * INV_CAP;
                x = fminf(fmaxf(x, -20.f), 20.f);
                float ex = __expf(2.f * x);
                float v = __fdividef(ex - 1.f, ex + 1.f) * CAP;
                if (diag) {
                    int kc = kt * BN + nt * 8 + 2 * t + (e & 1);
                    int qr = qr0 + ((e >> 1) << 3);
                    if (kc > qr) v = -1e30f;
                }
                acc[nt][e] = v;
                if (e < 2) mt0 = fmaxf(mt0, v); else mt1 = fmaxf(mt1, v);
            }
        }
        mt0 = fmaxf(mt0, __shfl_xor_sync(0xffffffffu, mt0, 1));
        mt0 = fmaxf(mt0, __shfl_xor_sync(0xffffffffu, mt0, 2));
        mt1 = fmaxf(mt1, __shfl_xor_sync(0xffffffffu, mt1, 1));
        mt1 = fmaxf(mt1, __shfl_xor_sync(0xffffffffu, mt1, 2));

        const float mn0 = fmaxf(m0, mt0), mn1 = fmaxf(m1, mt1);
        const float al0 = __expf(m0 - mn0), al1 = __expf(m1 - mn1);
        m0 = mn0; m1 = mn1;

        float rs0 = 0.f, rs1 = 0.f;
#pragma unroll
        for (int nt = 0; nt < 8; nt++) {
            acc[nt][0] = __expf(acc[nt][0] - mn0);
            acc[nt][1] = __expf(acc[nt][1] - mn0);
            acc[nt][2] = __expf(acc[nt][2] - mn1);
            acc[nt][3] = __expf(acc[nt][3] - mn1);
            rs0 += acc[nt][0] + acc[nt][1];
            rs1 += acc[nt][2] + acc[nt][3];
        }
        rs0 += __shfl_xor_sync(0xffffffffu, rs0, 1);
        rs0 += __shfl_xor_sync(0xffffffffu, rs0, 2);
        rs1 += __shfl_xor_sync(0xffffffffu, rs1, 1);
        rs1 += __shfl_xor_sync(0xffffffffu, rs1, 2);
        l0 = l0 * al0 + rs0;
        l1 = l1 * al1 + rs1;

#pragma unroll
        for (int ni = 0; ni < 16; ni++) {
            oacc[ni][0] *= al0; oacc[ni][1] *= al0;
            oacc[ni][2] *= al1; oacc[ni][3] *= al1;
        }

        // ---- store prefetched K -> alt buffer (frees kr regs) ----
        if (pf) {
#pragma unroll
            for (int ii = 0; ii < 4; ii++) {
                int idx = tid + ii * 256;
                int r = idx >> 4, u = idx & 15;
                int nI = r >> 3, gg = r & 7;
                uint32_t W[4] = { kr[ii].x, kr[ii].y, kr[ii].z, kr[ii].w };
#pragma unroll
                for (int j = 0; j < 4; j++) {
                    int v = 4 * u + j;
                    Kn[(nI * 8 + (v >> 3)) * 68 + bw(gg, v & 3, (v >> 2) & 1)] = W[j];
                }
            }
        }

        // ---- prefetch V(kt+1) into regs (latency hides behind PV) ----
        float4 va0[4], va1[4];
        if (pf) {
#pragma unroll
            for (int ii = 0; ii < 4; ii++) {
                int idx = tid + ii * 256;
                int kp = idx >> 5, c4 = idx & 31;
                const float* v0p = Vg + (size_t)((kt + 1) * BN + 2 * kp) * QKV_LD + c4 * 4;
                va0[ii] = *(const float4*)v0p;
                va1[ii] = *(const float4*)(v0p + QKV_LD);
            }
        }

        // ---- P -> smem (A-frag layout, warp-private) ----
#pragma unroll
        for (int nt = 0; nt < 8; nt++) {
            int ki = nt >> 1;
            int reg0 = 2 * (nt & 1);
            uint32_t* Pd = Ps + warp * 512 + ki * 128;
            Pd[aw(g, t, reg0)]     = pk(acc[nt][0], acc[nt][1]);
            Pd[aw(g, t, reg0 + 1)] = pk(acc[nt][2], acc[nt][3]);
        }
        __syncwarp();

        // ---- PV ----
#pragma unroll 2
        for (int ki = 0; ki < 4; ki++) {
            uint4 pa = *(const uint4*)(Ps + warp * 512 + ki * 128 + aRd);
            uint32_t af[4] = { pa.x, pa.y, pa.z, pa.w };
#pragma unroll
            for (int ni = 0; ni < 16; ni++) {
                uint2 vb2 = *(const uint2*)(Vc + (ni * 4 + ki) * 68 + bRd);
                uint32_t bf[2] = { vb2.x, vb2.y };
                mma_f16(oacc[ni], af, bf);
            }
        }

        // ---- store prefetched V -> alt buffer ----
        if (pf) {
#pragma unroll
            for (int ii = 0; ii < 4; ii++) {
                int idx = tid + ii * 256;
                int kp = idx >> 5, c4 = idx & 31;
                int ki = kp >> 3, kc = kp & 7;
                int reg = kc >> 2, e = kc & 3;
                float a0[4] = { va0[ii].x, va0[ii].y, va0[ii].z, va0[ii].w };
                float a1[4] = { va1[ii].x, va1[ii].y, va1[ii].z, va1[ii].w };
#pragma unroll
                for (int j = 0; j < 4; j++) {
                    int d = c4 * 4 + j;
                    Vn[((d >> 3) * 4 + ki) * 68 + bw(d & 7, e, reg)] = pk(a0[j], a1[j]);
                }
            }
        }
        __syncthreads();
    }

    // ---- epilogue ----
    const float inv0 = __fdividef(1.f, l0);
    const float inv1 = __fdividef(1.f, l1);
    float* o0 = out + (size_t)qr0 * HID + h * DH;
    float* o1 = out + (size_t)(qr0 + 8) * HID + h * DH;
#pragma unroll
    for (int ni = 0; ni < 16; ni++) {
        int col = ni * 8 + 2 * t;
        *(float2*)(o0 + col) = make_float2(oacc[ni][0] * inv0, oacc[ni][1] * inv0);
        *(float2*)(o1 + col) = make_float2(oacc[ni][2] * inv1, oacc[ni][3] * inv1);
    }
}

// ---------------------------------------------------------------------------
// Inputs (metadata order): hidden_states, cos, sin, attention_mask, wq, wk, wv, wo
// ---------------------------------------------------------------------------
extern "C" void kernel_launch(void* const* d_in, const int* in_sizes, int n_in,
                              void* d_out, int out_size)
{
    const float* hs   = (const float*)d_in[0];
    const float* cosp = (const float*)d_in[1];
    const float* sinp = (const float*)d_in[2];
    const float* wq   = (const float*)d_in[4];
    const float* wk   = (const float*)d_in[5];
    const float* wv   = (const float*)d_in[6];
    const float* wo   = (const float*)d_in[7];
    float* out = (float*)d_out;

    float* qkv = nullptr; uint32_t* qk16 = nullptr; float* attn = nullptr;
    cudaGetSymbolAddress((void**)&qkv,  g_qkv);
    cudaGetSymbolAddress((void**)&qk16, g_qk16);
    cudaGetSymbolAddress((void**)&attn, g_attn);

    cudaFuncSetAttribute(gemm_f16, cudaFuncAttributeMaxDynamicSharedMemorySize, GEMM_SMEM);
    cudaFuncSetAttribute(attn_mma, cudaFuncAttributeMaxDynamicSharedMemorySize, ATTN_SMEM);

    dim3 blk(256);
    // Fused QKV projection -> g_qkv [S,3072] (f32)
    gemm_f16<<<dim3(3072 / 64, S_LEN / 128), blk, GEMM_SMEM>>>(hs, wq, wk, wv, qkv, HID, QKV_LD);
    // RoPE + pack Q/K to fp16x2 dim-pairs
    rope_pack<<<S_LEN, 256>>>(qkv, qk16, cosp, sinp);
    // Flash attention
    attn_mma<<<dim3(S_LEN / BM, NH), blk, ATTN_SMEM>>>(qk16, qkv, attn);
    // Output projection
    gemm_f16<<<dim3(2048 / 64, S_LEN / 128), blk, GEMM_SMEM>>>(attn, wo, wo, wo, out, HID, HID);
}

// round 7
// speedup vs baseline: 5.6535x; 1.3577x over previous
#include <cuda_runtime.h>
#include <cuda_bf16.h>
#include <cuda_fp16.h>
#include <cstdint>

#define S_LEN   4096
#define HID     2048
#define NH      16
#define NKV     4
#define DH      128
#define QKV_LD  3072
#define QK16_LD 1280
#define Q_SCALE 0.08838834764831845f
#define INV_CAP (1.0f / 50.0f)
#define CAP     50.0f

// Scratch (device globals: no cudaMalloc allowed)
__device__ float    g_qkv[(size_t)S_LEN * QKV_LD];     // [S,3072] f32: Q | K | V
__device__ uint32_t g_qk16[(size_t)S_LEN * QK16_LD];   // [S,1280] fp16x2: Q(1024w) | K(256w)
__device__ uint32_t g_hs16[(size_t)S_LEN * 1024];      // hidden_states fp16 [4096,2048]
__device__ uint32_t g_w16[(size_t)3072 * 1024];        // wq|wk|wv fp16 [3072,2048]
__device__ uint32_t g_wo16[(size_t)2048 * 1024];       // wo fp16 [2048,2048]
__device__ uint32_t g_attn16[(size_t)S_LEN * 1024];    // attn out fp16 [4096,2048]

// ===========================================================================
// Helpers
// ===========================================================================
__device__ __forceinline__ uint32_t pk(float lo, float hi) {
    uint32_t d;
    asm("cvt.rn.f16x2.f32 %0, %1, %2;" : "=r"(d) : "f"(hi), "f"(lo));
    return d;
}
__device__ __forceinline__ void mma_f16(float* c, const uint32_t* a, const uint32_t* b) {
    asm volatile(
        "mma.sync.aligned.m16n8k16.row.col.f32.f16.f16.f32 "
        "{%0,%1,%2,%3}, {%4,%5,%6,%7}, {%8,%9}, {%0,%1,%2,%3};"
        : "+f"(c[0]), "+f"(c[1]), "+f"(c[2]), "+f"(c[3])
        : "r"(a[0]), "r"(a[1]), "r"(a[2]), "r"(a[3]), "r"(b[0]), "r"(b[1]));
}
__device__ __forceinline__ uint32_t smem_u32(const void* p) {
    uint32_t a;
    asm("{ .reg .u64 t; cvta.to.shared.u64 t, %1; cvt.u32.u64 %0, t; }"
        : "=r"(a) : "l"(p));
    return a;
}
#define LDSM4(r0, r1, r2, r3, addr) \
    asm volatile("ldmatrix.sync.aligned.m8n8.x4.shared.b16 {%0,%1,%2,%3}, [%4];" \
        : "=r"(r0), "=r"(r1), "=r"(r2), "=r"(r3) : "r"(addr))
#define CP_A16(saddr, gptr) \
    asm volatile("cp.async.cg.shared.global [%0], [%1], 16;" :: "r"(saddr), "l"(gptr))
#define CP_COMMIT() asm volatile("cp.async.commit_group;" ::: "memory")
#define CP_WAIT(n)  asm volatile("cp.async.wait_group %0;" :: "n"(n) : "memory")

// Fragment-layout word offsets (attn kernel, validated R4-R6).
__device__ __forceinline__ int aw(int g, int e, int reg) {
    return ((g * 16 + e * 4 + reg) ^ (g * 4));
}
__device__ __forceinline__ int bw(int g, int e, int reg) {
    return (((g * 4 + e) * 2 + reg) ^ ((g & 4) >> 1));
}

// ---------------------------------------------------------------------------
// f32 -> fp16x2 bulk convert (vectorized)
// ---------------------------------------------------------------------------
__global__ void cvt16(const float* __restrict__ src, uint32_t* __restrict__ dst, int n4)
{
    int i = blockIdx.x * 256 + threadIdx.x;
    if (i < n4) {
        float4 v = ((const float4*)src)[i];
        ((uint2*)dst)[i] = make_uint2(pk(v.x, v.y), pk(v.z, v.w));
    }
}

// ===========================================================================
// FP16 GEMM, cp.async + ldmatrix. C[m,n] = sum_k A[m,k]*B[n,k], both fp16
// row-major [.,Kd]. Tile 128m x 64n x 64k, 3-stage pipeline, 8 warps (4m x 2n).
// smem layout per stage: A 128 rows x 128B, B 64 rows x 128B; 16B-unit swizzle
// c16 ^= (row & 7).
// ===========================================================================
#define KC 64
#define STAGES 3
#define AST 16384
#define BST 8192
#define STG (AST + BST)
#define GEMM_SMEM (STAGES * STG)

__global__ __launch_bounds__(256, 2) void gemm_h(
    const __half* __restrict__ A, const __half* __restrict__ B,
    float* __restrict__ C, int Kd, int ldc)
{
    extern __shared__ __align__(128) char smc[];
    const uint32_t sb = smem_u32(smc);

    const int tid  = threadIdx.x;
    const int lane = tid & 31;
    const int warp = tid >> 5;
    const int wm   = warp >> 1;          // 0..3
    const int wn   = warp & 1;           // 0..1
    const int bm   = blockIdx.y * 128;
    const int bnG  = blockIdx.x * 64;
    const int NC   = Kd / KC;

    // loader geometry: thread -> (row = idx>>3, c16 = idx&7), 16B each
    const int lrow = tid >> 3;           // 0..31
    const int lc16 = tid & 7;
    const __half* Ag = A + (size_t)(bm + lrow) * Kd + lc16 * 8;
    const __half* Bg = B + (size_t)(bnG + lrow) * Kd + lc16 * 8;

    // per-thread swizzled smem byte offsets for the 4 A rows / 2 B rows
    uint32_t soA[4], soB[2];
#pragma unroll
    for (int it = 0; it < 4; it++) {
        int row = lrow + it * 32;
        soA[it] = (uint32_t)(row * 128 + ((lc16 ^ (row & 7)) << 4));
    }
#pragma unroll
    for (int it = 0; it < 2; it++) {
        int row = lrow + it * 32;
        soB[it] = (uint32_t)(row * 128 + ((lc16 ^ (row & 7)) << 4));
    }

    // ldmatrix per-lane geometry
    const int l15 = lane & 15;
    const int lh  = lane >> 4;           // 0: k-block lo, 1: k-block hi
    int aRow[2], bRow[2];
#pragma unroll
    for (int mi = 0; mi < 2; mi++) aRow[mi] = wm * 32 + mi * 16 + l15;
#pragma unroll
    for (int nt = 0; nt < 2; nt++) bRow[nt] = wn * 32 + nt * 16 + l15;

    float acc[2][4][4];
#pragma unroll
    for (int i = 0; i < 2; i++)
#pragma unroll
        for (int j = 0; j < 4; j++)
#pragma unroll
            for (int e = 0; e < 4; e++) acc[i][j][e] = 0.f;

    // ---- prologue: issue stages 0..STAGES-2 ----
#pragma unroll
    for (int s = 0; s < STAGES - 1; s++) {
        const uint32_t sA = sb + s * STG;
        const uint32_t sB = sA + AST;
        const size_t ko = (size_t)s * KC;
#pragma unroll
        for (int it = 0; it < 4; it++)
            CP_A16(sA + soA[it], Ag + (size_t)(it * 32) * Kd + ko);
#pragma unroll
        for (int it = 0; it < 2; it++)
            CP_A16(sB + soB[it], Bg + (size_t)(it * 32) * Kd + ko);
        CP_COMMIT();
    }

    // ---- main loop ----
    for (int ic = 0; ic < NC; ic++) {
        // issue stage ic+STAGES-1
        if (ic + STAGES - 1 < NC) {
            const int s = (ic + STAGES - 1) % STAGES;
            const uint32_t sA = sb + s * STG;
            const uint32_t sB = sA + AST;
            const size_t ko = (size_t)(ic + STAGES - 1) * KC;
#pragma unroll
            for (int it = 0; it < 4; it++)
                CP_A16(sA + soA[it], Ag + (size_t)(it * 32) * Kd + ko);
#pragma unroll
            for (int it = 0; it < 2; it++)
                CP_A16(sB + soB[it], Bg + (size_t)(it * 32) * Kd + ko);
        }
        CP_COMMIT();
        CP_WAIT(STAGES - 1);
        __syncthreads();

        const uint32_t sA = sb + (ic % STAGES) * STG;
        const uint32_t sB = sA + AST;

#pragma unroll
        for (int ki = 0; ki < 4; ki++) {
            uint32_t af[2][4], bv[2][4];
#pragma unroll
            for (int mi = 0; mi < 2; mi++) {
                int kb = ki * 2 + lh;
                uint32_t ad = sA + aRow[mi] * 128 + (((kb ^ (aRow[mi] & 7))) << 4);
                LDSM4(af[mi][0], af[mi][1], af[mi][2], af[mi][3], ad);
            }
#pragma unroll
            for (int nt = 0; nt < 2; nt++) {
                int kb = ki * 2 + lh;
                uint32_t bd = sB + bRow[nt] * 128 + (((kb ^ (bRow[nt] & 7))) << 4);
                LDSM4(bv[nt][0], bv[nt][1], bv[nt][2], bv[nt][3], bd);
            }
#pragma unroll
            for (int mi = 0; mi < 2; mi++)
#pragma unroll
                for (int j = 0; j < 4; j++) {
                    // n8 block j: nt = j>>1, hi = j&1
                    uint32_t bf[2] = { bv[j >> 1][(j & 1)], bv[j >> 1][2 + (j & 1)] };
                    mma_f16(acc[mi][j], af[mi], bf);
                }
        }
        __syncthreads();
    }

    // ---- epilogue ----
    const int g = lane >> 2, t = lane & 3;
#pragma unroll
    for (int mi = 0; mi < 2; mi++)
#pragma unroll
        for (int j = 0; j < 4; j++) {
            const int row = bm + wm * 32 + mi * 16 + g;
            const int col = bnG + wn * 32 + j * 8 + t * 2;
            float* p0 = C + (size_t)row * ldc + col;
            float* p1 = C + (size_t)(row + 8) * ldc + col;
            *(float2*)p0 = make_float2(acc[mi][j][0], acc[mi][j][1]);
            *(float2*)p1 = make_float2(acc[mi][j][2], acc[mi][j][3]);
        }
}

// ---------------------------------------------------------------------------
// RoPE + Q scale -> packed fp16x2 dim-pairs [S][1280]: Q(1024w) | K(256w)
// ---------------------------------------------------------------------------
__global__ void rope_pack(const float* __restrict__ qkv, uint32_t* __restrict__ qk16,
                          const float* __restrict__ cosp, const float* __restrict__ sinp)
{
    const int s = blockIdx.x;
    const float* c  = cosp + (size_t)s * DH;
    const float* sn = sinp + (size_t)s * DH;
    const float* row = qkv + (size_t)s * QKV_LD;
    uint32_t* orow = qk16 + (size_t)s * QK16_LD;
    for (int i = threadIdx.x; i < 20 * 32; i += blockDim.x) {
        int hh = i >> 5;
        int c0 = i & 31;
        int d0 = 2 * c0;
        int base = (hh < 16) ? hh * 128 : (2048 + (hh - 16) * 128);
        float x1a = row[base + d0],      x1b = row[base + d0 + 1];
        float x2a = row[base + d0 + 64], x2b = row[base + d0 + 65];
        float y1a = x1a * c[d0]      - x2a * sn[d0];
        float y1b = x1b * c[d0 + 1]  - x2b * sn[d0 + 1];
        float y2a = x2a * c[d0 + 64] + x1a * sn[d0 + 64];
        float y2b = x2b * c[d0 + 65] + x1b * sn[d0 + 65];
        if (hh < 16) { y1a *= Q_SCALE; y1b *= Q_SCALE; y2a *= Q_SCALE; y2b *= Q_SCALE; }
        int obase = (hh < 16) ? hh * 64 : (1024 + (hh - 16) * 64);
        orow[obase + c0]      = pk(y1a, y1b);
        orow[obase + 32 + c0] = pk(y2a, y2b);
    }
}

// ===========================================================================
// Flash attention, fp16 mma.sync (layouts validated R4-R6). Emits fp16 output.
// ===========================================================================
#define BM 128
#define BN 64
#define AQ_OFF 0
#define AK_OFF 8192
#define AV_OFF (8192 + 2 * 4352)
#define AP_OFF (8192 + 4 * 4352)
#define ATTN_WORDS (8192 + 4 * 4352 + 4096)
#define ATTN_SMEM (ATTN_WORDS * 4)

__global__ __launch_bounds__(256, 1) void attn_mma(
    const uint32_t* __restrict__ qk16, const float* __restrict__ qkv,
    uint32_t* __restrict__ out16)
{
    extern __shared__ uint32_t sw[];
    uint32_t* Qs = sw + AQ_OFF;
    uint32_t* Kb[2] = { sw + AK_OFF, sw + AK_OFF + 4352 };
    uint32_t* Vb[2] = { sw + AV_OFF, sw + AV_OFF + 4352 };
    uint32_t* Ps = sw + AP_OFF;

    const int tid  = threadIdx.x;
    const int lane = tid & 31;
    const int warp = tid >> 5;
    const int qb   = (int)gridDim.x - 1 - (int)blockIdx.x;
    const int h    = blockIdx.y;
    const int kvg  = h >> 2;

    const int g = lane >> 2, t = lane & 3;
    const int aRd = (g * 16 + t * 4) ^ (g * 4);
    const int bRd = (lane * 2) ^ ((g & 4) >> 1);

    const uint32_t* Qg = qk16 + h * 64;
    const uint32_t* Kg = qk16 + 1024 + kvg * 64;
    const float*    Vg = qkv + 2560 + kvg * DH;

    for (int i = tid; i < BM * 16; i += 256) {
        int r = i >> 4, u = i & 15;
        uint4 U = *(const uint4*)(Qg + (size_t)(qb * BM + r) * QK16_LD + u * 4);
        int mi = r >> 4, rr = r & 15, hi = rr >> 3, gg = rr & 7;
        uint32_t* Qd = Qs + mi * 1024;
        uint32_t W[4] = { U.x, U.y, U.z, U.w };
#pragma unroll
        for (int j = 0; j < 4; j++) {
            int v = 4 * u + j;
            Qd[(v >> 3) * 128 + aw(gg, v & 3, hi + 2 * ((v >> 2) & 1))] = W[j];
        }
    }

    {
        for (int i = tid; i < BN * 16; i += 256) {
            int r = i >> 4, u = i & 15;
            uint4 U = *(const uint4*)(Kg + (size_t)r * QK16_LD + u * 4);
            int nI = r >> 3, gg = r & 7;
            uint32_t W[4] = { U.x, U.y, U.z, U.w };
#pragma unroll
            for (int j = 0; j < 4; j++) {
                int v = 4 * u + j;
                Kb[0][(nI * 8 + (v >> 3)) * 68 + bw(gg, v & 3, (v >> 2) & 1)] = W[j];
            }
        }
        for (int i = tid; i < 32 * 32; i += 256) {
            int kp = i >> 5, c4 = i & 31;
            const float* v0p = Vg + (size_t)(2 * kp) * QKV_LD + c4 * 4;
            float4 v0 = *(const float4*)v0p;
            float4 v1 = *(const float4*)(v0p + QKV_LD);
            int ki = kp >> 3, kc = kp & 7;
            int reg = kc >> 2, e = kc & 3;
            float a0[4] = { v0.x, v0.y, v0.z, v0.w };
            float a1[4] = { v1.x, v1.y, v1.z, v1.w };
#pragma unroll
            for (int j = 0; j < 4; j++) {
                int d = c4 * 4 + j;
                Vb[0][((d >> 3) * 4 + ki) * 68 + bw(d & 7, e, reg)] = pk(a0[j], a1[j]);
            }
        }
    }
    __syncthreads();

    float oacc[16][4];
#pragma unroll
    for (int i = 0; i < 16; i++)
#pragma unroll
        for (int e = 0; e < 4; e++) oacc[i][e] = 0.f;
    float m0 = -1e30f, m1 = -1e30f, l0 = 0.f, l1 = 0.f;

    const int qr0 = qb * BM + warp * 16 + g;
    const int ntiles = 2 * qb + 2;

    for (int kt = 0; kt < ntiles; kt++) {
        const bool pf = (kt + 1 < ntiles);
        const uint32_t* Kc = Kb[kt & 1];
        const uint32_t* Vc = Vb[kt & 1];
        uint32_t* Kn = Kb[(kt + 1) & 1];
        uint32_t* Vn = Vb[(kt + 1) & 1];

        uint4 kr[4];
        if (pf) {
#pragma unroll
            for (int ii = 0; ii < 4; ii++) {
                int idx = tid + ii * 256;
                int r = idx >> 4, u = idx & 15;
                kr[ii] = *(const uint4*)(Kg + (size_t)((kt + 1) * BN + r) * QK16_LD + u * 4);
            }
        }

        float acc[8][4];
#pragma unroll
        for (int nt = 0; nt < 8; nt++)
#pragma unroll
            for (int e = 0; e < 4; e++) acc[nt][e] = 0.f;
#pragma unroll 4
        for (int ki = 0; ki < 8; ki++) {
            uint4 qa = *(const uint4*)(Qs + warp * 1024 + ki * 128 + aRd);
            uint32_t af[4] = { qa.x, qa.y, qa.z, qa.w };
#pragma unroll
            for (int nt = 0; nt < 8; nt++) {
                uint2 kb2 = *(const uint2*)(Kc + (nt * 8 + ki) * 68 + bRd);
                uint32_t bf[2] = { kb2.x, kb2.y };
                mma_f16(acc[nt], af, bf);
            }
        }

        const bool diag = (kt >= 2 * qb);
        float mt0 = -1e30f, mt1 = -1e30f;
#pragma unroll
        for (int nt = 0; nt < 8; nt++) {
#pragma unroll
            for (int e = 0; e < 4; e++) {
                float x = acc[nt][e] * INV_CAP;
                x = fminf(fmaxf(x, -20.f), 20.f);
                float ex = __expf(2.f * x);
                float v = __fdividef(ex - 1.f, ex + 1.f) * CAP;
                if (diag) {
                    int kc = kt * BN + nt * 8 + 2 * t + (e & 1);
                    int qr = qr0 + ((e >> 1) << 3);
                    if (kc > qr) v = -1e30f;
                }
                acc[nt][e] = v;
                if (e < 2) mt0 = fmaxf(mt0, v); else mt1 = fmaxf(mt1, v);
            }
        }
        mt0 = fmaxf(mt0, __shfl_xor_sync(0xffffffffu, mt0, 1));
        mt0 = fmaxf(mt0, __shfl_xor_sync(0xffffffffu, mt0, 2));
        mt1 = fmaxf(mt1, __shfl_xor_sync(0xffffffffu, mt1, 1));
        mt1 = fmaxf(mt1, __shfl_xor_sync(0xffffffffu, mt1, 2));

        const float mn0 = fmaxf(m0, mt0), mn1 = fmaxf(m1, mt1);
        const float al0 = __expf(m0 - mn0), al1 = __expf(m1 - mn1);
        m0 = mn0; m1 = mn1;

        float rs0 = 0.f, rs1 = 0.f;
#pragma unroll
        for (int nt = 0; nt < 8; nt++) {
            acc[nt][0] = __expf(acc[nt][0] - mn0);
            acc[nt][1] = __expf(acc[nt][1] - mn0);
            acc[nt][2] = __expf(acc[nt][2] - mn1);
            acc[nt][3] = __expf(acc[nt][3] - mn1);
            rs0 += acc[nt][0] + acc[nt][1];
            rs1 += acc[nt][2] + acc[nt][3];
        }
        rs0 += __shfl_xor_sync(0xffffffffu, rs0, 1);
        rs0 += __shfl_xor_sync(0xffffffffu, rs0, 2);
        rs1 += __shfl_xor_sync(0xffffffffu, rs1, 1);
        rs1 += __shfl_xor_sync(0xffffffffu, rs1, 2);
        l0 = l0 * al0 + rs0;
        l1 = l1 * al1 + rs1;

#pragma unroll
        for (int ni = 0; ni < 16; ni++) {
            oacc[ni][0] *= al0; oacc[ni][1] *= al0;
            oacc[ni][2] *= al1; oacc[ni][3] *= al1;
        }

        if (pf) {
#pragma unroll
            for (int ii = 0; ii < 4; ii++) {
                int idx = tid + ii * 256;
                int r = idx >> 4, u = idx & 15;
                int nI = r >> 3, gg = r & 7;
                uint32_t W[4] = { kr[ii].x, kr[ii].y, kr[ii].z, kr[ii].w };
#pragma unroll
                for (int j = 0; j < 4; j++) {
                    int v = 4 * u + j;
                    Kn[(nI * 8 + (v >> 3)) * 68 + bw(gg, v & 3, (v >> 2) & 1)] = W[j];
                }
            }
        }

        float4 va0[4], va1[4];
        if (pf) {
#pragma unroll
            for (int ii = 0; ii < 4; ii++) {
                int idx = tid + ii * 256;
                int kp = idx >> 5, c4 = idx & 31;
                const float* v0p = Vg + (size_t)((kt + 1) * BN + 2 * kp) * QKV_LD + c4 * 4;
                va0[ii] = *(const float4*)v0p;
                va1[ii] = *(const float4*)(v0p + QKV_LD);
            }
        }

#pragma unroll
        for (int nt = 0; nt < 8; nt++) {
            int ki = nt >> 1;
            int reg0 = 2 * (nt & 1);
            uint32_t* Pd = Ps + warp * 512 + ki * 128;
            Pd[aw(g, t, reg0)]     = pk(acc[nt][0], acc[nt][1]);
            Pd[aw(g, t, reg0 + 1)] = pk(acc[nt][2], acc[nt][3]);
        }
        __syncwarp();

#pragma unroll 2
        for (int ki = 0; ki < 4; ki++) {
            uint4 pa = *(const uint4*)(Ps + warp * 512 + ki * 128 + aRd);
            uint32_t af[4] = { pa.x, pa.y, pa.z, pa.w };
#pragma unroll
            for (int ni = 0; ni < 16; ni++) {
                uint2 vb2 = *(const uint2*)(Vc + (ni * 4 + ki) * 68 + bRd);
                uint32_t bf[2] = { vb2.x, vb2.y };
                mma_f16(oacc[ni], af, bf);
            }
        }

        if (pf) {
#pragma unroll
            for (int ii = 0; ii < 4; ii++) {
                int idx = tid + ii * 256;
                int kp = idx >> 5, c4 = idx & 31;
                int ki = kp >> 3, kc = kp & 7;
                int reg = kc >> 2, e = kc & 3;
                float a0[4] = { va0[ii].x, va0[ii].y, va0[ii].z, va0[ii].w };
                float a1[4] = { va1[ii].x, va1[ii].y, va1[ii].z, va1[ii].w };
#pragma unroll
                for (int j = 0; j < 4; j++) {
                    int d = c4 * 4 + j;
                    Vn[((d >> 3) * 4 + ki) * 68 + bw(d & 7, e, reg)] = pk(a0[j], a1[j]);
                }
            }
        }
        __syncthreads();
    }

    // ---- epilogue: fp16 output ----
    const float inv0 = __fdividef(1.f, l0);
    const float inv1 = __fdividef(1.f, l1);
    uint32_t* o0 = out16 + (size_t)qr0 * 1024 + h * 64 + t;
    uint32_t* o1 = out16 + (size_t)(qr0 + 8) * 1024 + h * 64 + t;
#pragma unroll
    for (int ni = 0; ni < 16; ni++) {
        o0[ni * 4] = pk(oacc[ni][0] * inv0, oacc[ni][1] * inv0);
        o1[ni * 4] = pk(oacc[ni][2] * inv1, oacc[ni][3] * inv1);
    }
}

// ---------------------------------------------------------------------------
// Inputs (metadata order): hidden_states, cos, sin, attention_mask, wq, wk, wv, wo
// ---------------------------------------------------------------------------
extern "C" void kernel_launch(void* const* d_in, const int* in_sizes, int n_in,
                              void* d_out, int out_size)
{
    const float* hs   = (const float*)d_in[0];
    const float* cosp = (const float*)d_in[1];
    const float* sinp = (const float*)d_in[2];
    const float* wq   = (const float*)d_in[4];
    const float* wk   = (const float*)d_in[5];
    const float* wv   = (const float*)d_in[6];
    const float* wo   = (const float*)d_in[7];
    float* out = (float*)d_out;

    float* qkv = nullptr; uint32_t* qk16 = nullptr;
    uint32_t* hs16 = nullptr; uint32_t* w16 = nullptr;
    uint32_t* wo16 = nullptr; uint32_t* attn16 = nullptr;
    cudaGetSymbolAddress((void**)&qkv,    g_qkv);
    cudaGetSymbolAddress((void**)&qk16,   g_qk16);
    cudaGetSymbolAddress((void**)&hs16,   g_hs16);
    cudaGetSymbolAddress((void**)&w16,    g_w16);
    cudaGetSymbolAddress((void**)&wo16,   g_wo16);
    cudaGetSymbolAddress((void**)&attn16, g_attn16);

    cudaFuncSetAttribute(gemm_h, cudaFuncAttributeMaxDynamicSharedMemorySize, GEMM_SMEM);
    cudaFuncSetAttribute(attn_mma, cudaFuncAttributeMaxDynamicSharedMemorySize, ATTN_SMEM);

    dim3 blk(256);
    // fp16 pre-conversion
    cvt16<<<(S_LEN * HID / 4 + 255) / 256, blk>>>(hs, hs16, S_LEN * HID / 4);
    cvt16<<<(2048 * HID / 4 + 255) / 256, blk>>>(wq, w16, 2048 * HID / 4);
    cvt16<<<(512 * HID / 4 + 255) / 256, blk>>>(wk, w16 + (size_t)2048 * 1024, 512 * HID / 4);
    cvt16<<<(512 * HID / 4 + 255) / 256, blk>>>(wv, w16 + (size_t)2560 * 1024, 512 * HID / 4);
    cvt16<<<(2048 * HID / 4 + 255) / 256, blk>>>(wo, wo16, 2048 * HID / 4);

    // Fused QKV projection -> g_qkv [S,3072] (f32)
    gemm_h<<<dim3(3072 / 64, S_LEN / 128), blk, GEMM_SMEM>>>(
        (const __half*)hs16, (const __half*)w16, qkv, HID, QKV_LD);
    // RoPE + pack Q/K
    rope_pack<<<S_LEN, 256>>>(qkv, qk16, cosp, sinp);
    // Flash attention -> fp16
    attn_mma<<<dim3(S_LEN / BM, NH), blk, ATTN_SMEM>>>(qk16, qkv, attn16);
    // Output projection
    gemm_h<<<dim3(2048 / 64, S_LEN / 128), blk, GEMM_SMEM>>>(
        (const __half*)attn16, (const __half*)wo16, out, HID, HID);
}

// round 8
// speedup vs baseline: 6.5172x; 1.1528x over previous
#include <cuda_runtime.h>
#include <cuda_bf16.h>
#include <cuda_fp16.h>
#include <cstdint>

#define S_LEN   4096
#define HID     2048
#define NH      16
#define NKV     4
#define DH      128
#define QKV_LD  3072
#define QK16_LD 1280
#define Q_SCALE 0.08838834764831845f
#define INV_CAP (1.0f / 50.0f)
#define CAP     50.0f

// Scratch (device globals: no cudaMalloc allowed)
__device__ float    g_qkv[(size_t)S_LEN * QKV_LD];     // [S,3072] f32: Q | K | V
__device__ uint32_t g_qk16[(size_t)S_LEN * QK16_LD];   // [S,1280] fp16x2: Q(1024w) | K(256w)
__device__ uint32_t g_v16[(size_t)S_LEN * 256];        // [S,256w] fp16 V rows (4 kv heads x 64w)
__device__ uint32_t g_hs16[(size_t)S_LEN * 1024];      // hidden_states fp16
__device__ uint32_t g_w16[(size_t)3072 * 1024];        // wq|wk|wv fp16
__device__ uint32_t g_wo16[(size_t)2048 * 1024];       // wo fp16
__device__ uint32_t g_attn16[(size_t)S_LEN * 1024];    // attn out fp16

// ===========================================================================
// Helpers
// ===========================================================================
__device__ __forceinline__ uint32_t pk(float lo, float hi) {
    uint32_t d;
    asm("cvt.rn.f16x2.f32 %0, %1, %2;" : "=r"(d) : "f"(hi), "f"(lo));
    return d;
}
__device__ __forceinline__ void mma_f16(float* c, const uint32_t* a, const uint32_t* b) {
    asm volatile(
        "mma.sync.aligned.m16n8k16.row.col.f32.f16.f16.f32 "
        "{%0,%1,%2,%3}, {%4,%5,%6,%7}, {%8,%9}, {%0,%1,%2,%3};"
        : "+f"(c[0]), "+f"(c[1]), "+f"(c[2]), "+f"(c[3])
        : "r"(a[0]), "r"(a[1]), "r"(a[2]), "r"(a[3]), "r"(b[0]), "r"(b[1]));
}
__device__ __forceinline__ uint32_t smem_u32(const void* p) {
    uint32_t a;
    asm("{ .reg .u64 t; cvta.to.shared.u64 t, %1; cvt.u32.u64 %0, t; }"
        : "=r"(a) : "l"(p));
    return a;
}
#define LDSM4(r0, r1, r2, r3, addr) \
    asm volatile("ldmatrix.sync.aligned.m8n8.x4.shared.b16 {%0,%1,%2,%3}, [%4];" \
        : "=r"(r0), "=r"(r1), "=r"(r2), "=r"(r3) : "r"(addr))
#define LDSM4T(r0, r1, r2, r3, addr) \
    asm volatile("ldmatrix.sync.aligned.m8n8.x4.trans.shared.b16 {%0,%1,%2,%3}, [%4];" \
        : "=r"(r0), "=r"(r1), "=r"(r2), "=r"(r3) : "r"(addr))
#define CP_A16(saddr, gptr) \
    asm volatile("cp.async.cg.shared.global [%0], [%1], 16;" :: "r"(saddr), "l"(gptr))
#define CP_COMMIT() asm volatile("cp.async.commit_group;" ::: "memory")
#define CP_WAIT(n)  asm volatile("cp.async.wait_group %0;" :: "n"(n) : "memory")

// ---------------------------------------------------------------------------
// f32 -> fp16x2 bulk convert
// ---------------------------------------------------------------------------
__global__ void cvt16(const float* __restrict__ src, uint32_t* __restrict__ dst, int n4)
{
    int i = blockIdx.x * 256 + threadIdx.x;
    if (i < n4) {
        float4 v = ((const float4*)src)[i];
        ((uint2*)dst)[i] = make_uint2(pk(v.x, v.y), pk(v.z, v.w));
    }
}

// ===========================================================================
// FP16 GEMM, cp.async + ldmatrix (unchanged from Round 7 — ~94% of rate)
// ===========================================================================
#define KC 64
#define STAGES 3
#define AST 16384
#define BST 8192
#define STG (AST + BST)
#define GEMM_SMEM (STAGES * STG)

__global__ __launch_bounds__(256, 2) void gemm_h(
    const __half* __restrict__ A, const __half* __restrict__ B,
    float* __restrict__ C, int Kd, int ldc)
{
    extern __shared__ __align__(128) char smc[];
    const uint32_t sb = smem_u32(smc);

    const int tid  = threadIdx.x;
    const int lane = tid & 31;
    const int warp = tid >> 5;
    const int wm   = warp >> 1;
    const int wn   = warp & 1;
    const int bm   = blockIdx.y * 128;
    const int bnG  = blockIdx.x * 64;
    const int NC   = Kd / KC;

    const int lrow = tid >> 3;
    const int lc16 = tid & 7;
    const __half* Ag = A + (size_t)(bm + lrow) * Kd + lc16 * 8;
    const __half* Bg = B + (size_t)(bnG + lrow) * Kd + lc16 * 8;

    uint32_t soA[4], soB[2];
#pragma unroll
    for (int it = 0; it < 4; it++) {
        int row = lrow + it * 32;
        soA[it] = (uint32_t)(row * 128 + ((lc16 ^ (row & 7)) << 4));
    }
#pragma unroll
    for (int it = 0; it < 2; it++) {
        int row = lrow + it * 32;
        soB[it] = (uint32_t)(row * 128 + ((lc16 ^ (row & 7)) << 4));
    }

    const int l15 = lane & 15;
    const int lh  = lane >> 4;
    int aRow[2], bRow[2];
#pragma unroll
    for (int mi = 0; mi < 2; mi++) aRow[mi] = wm * 32 + mi * 16 + l15;
#pragma unroll
    for (int nt = 0; nt < 2; nt++) bRow[nt] = wn * 32 + nt * 16 + l15;

    float acc[2][4][4];
#pragma unroll
    for (int i = 0; i < 2; i++)
#pragma unroll
        for (int j = 0; j < 4; j++)
#pragma unroll
            for (int e = 0; e < 4; e++) acc[i][j][e] = 0.f;

#pragma unroll
    for (int s = 0; s < STAGES - 1; s++) {
        const uint32_t sA = sb + s * STG;
        const uint32_t sB = sA + AST;
        const size_t ko = (size_t)s * KC;
#pragma unroll
        for (int it = 0; it < 4; it++)
            CP_A16(sA + soA[it], Ag + (size_t)(it * 32) * Kd + ko);
#pragma unroll
        for (int it = 0; it < 2; it++)
            CP_A16(sB + soB[it], Bg + (size_t)(it * 32) * Kd + ko);
        CP_COMMIT();
    }

    for (int ic = 0; ic < NC; ic++) {
        if (ic + STAGES - 1 < NC) {
            const int s = (ic + STAGES - 1) % STAGES;
            const uint32_t sA = sb + s * STG;
            const uint32_t sB = sA + AST;
            const size_t ko = (size_t)(ic + STAGES - 1) * KC;
#pragma unroll
            for (int it = 0; it < 4; it++)
                CP_A16(sA + soA[it], Ag + (size_t)(it * 32) * Kd + ko);
#pragma unroll
            for (int it = 0; it < 2; it++)
                CP_A16(sB + soB[it], Bg + (size_t)(it * 32) * Kd + ko);
        }
        CP_COMMIT();
        CP_WAIT(STAGES - 1);
        __syncthreads();

        const uint32_t sA = sb + (ic % STAGES) * STG;
        const uint32_t sB = sA + AST;

#pragma unroll
        for (int ki = 0; ki < 4; ki++) {
            uint32_t af[2][4], bv[2][4];
#pragma unroll
            for (int mi = 0; mi < 2; mi++) {
                int kb = ki * 2 + lh;
                uint32_t ad = sA + aRow[mi] * 128 + (((kb ^ (aRow[mi] & 7))) << 4);
                LDSM4(af[mi][0], af[mi][1], af[mi][2], af[mi][3], ad);
            }
#pragma unroll
            for (int nt = 0; nt < 2; nt++) {
                int kb = ki * 2 + lh;
                uint32_t bd = sB + bRow[nt] * 128 + (((kb ^ (bRow[nt] & 7))) << 4);
                LDSM4(bv[nt][0], bv[nt][1], bv[nt][2], bv[nt][3], bd);
            }
#pragma unroll
            for (int mi = 0; mi < 2; mi++)
#pragma unroll
                for (int j = 0; j < 4; j++) {
                    uint32_t bf[2] = { bv[j >> 1][(j & 1)], bv[j >> 1][2 + (j & 1)] };
                    mma_f16(acc[mi][j], af[mi], bf);
                }
        }
        __syncthreads();
    }

    const int g = lane >> 2, t = lane & 3;
#pragma unroll
    for (int mi = 0; mi < 2; mi++)
#pragma unroll
        for (int j = 0; j < 4; j++) {
            const int row = bm + wm * 32 + mi * 16 + g;
            const int col = bnG + wn * 32 + j * 8 + t * 2;
            float* p0 = C + (size_t)row * ldc + col;
            float* p1 = C + (size_t)(row + 8) * ldc + col;
            *(float2*)p0 = make_float2(acc[mi][j][0], acc[mi][j][1]);
            *(float2*)p1 = make_float2(acc[mi][j][2], acc[mi][j][3]);
        }
}

// ---------------------------------------------------------------------------
// RoPE + Q scale -> g_qk16 (Q,K fp16 rows); V -> g_v16 (fp16 rows, no rope)
// ---------------------------------------------------------------------------
__global__ void rope_pack(const float* __restrict__ qkv,
                          uint32_t* __restrict__ qk16, uint32_t* __restrict__ v16,
                          const float* __restrict__ cosp, const float* __restrict__ sinp)
{
    const int s = blockIdx.x;
    const float* c  = cosp + (size_t)s * DH;
    const float* sn = sinp + (size_t)s * DH;
    const float* row = qkv + (size_t)s * QKV_LD;
    uint32_t* orow = qk16 + (size_t)s * QK16_LD;
    uint32_t* vrow = v16 + (size_t)s * 256;
    for (int i = threadIdx.x; i < 24 * 32; i += blockDim.x) {
        int hh = i >> 5;
        int c0 = i & 31;
        if (hh < 20) {
            int d0 = 2 * c0;
            int base = (hh < 16) ? hh * 128 : (2048 + (hh - 16) * 128);
            float x1a = row[base + d0],      x1b = row[base + d0 + 1];
            float x2a = row[base + d0 + 64], x2b = row[base + d0 + 65];
            float y1a = x1a * c[d0]      - x2a * sn[d0];
            float y1b = x1b * c[d0 + 1]  - x2b * sn[d0 + 1];
            float y2a = x2a * c[d0 + 64] + x1a * sn[d0 + 64];
            float y2b = x2b * c[d0 + 65] + x1b * sn[d0 + 65];
            if (hh < 16) { y1a *= Q_SCALE; y1b *= Q_SCALE; y2a *= Q_SCALE; y2b *= Q_SCALE; }
            int obase = (hh < 16) ? hh * 64 : (1024 + (hh - 16) * 64);
            orow[obase + c0]      = pk(y1a, y1b);
            orow[obase + 32 + c0] = pk(y2a, y2b);
        } else {
            int base = 2560 + (hh - 20) * 128;
            int obase = (hh - 20) * 64;
            vrow[obase + c0]      = pk(row[base + 2 * c0],      row[base + 2 * c0 + 1]);
            vrow[obase + 32 + c0] = pk(row[base + 64 + 2 * c0], row[base + 64 + 2 * c0 + 1]);
        }
    }
}

// ===========================================================================
// Flash attention: cp.async + ldmatrix, 2 CTAs/SM. BM=128, BN=64, 8 warps.
// smem: Q 32K | K0 16K | K1 16K | V0 16K | V1 16K | P 16K  = 112 KB
// ===========================================================================
#define ATTN_SMEM 114688
#define SQ_OFF 0
#define SK_OFF 32768
#define SV_OFF 65536
#define SP_OFF 98304

__global__ __launch_bounds__(256, 2) void attn_mma(
    const uint32_t* __restrict__ qk16, const uint32_t* __restrict__ v16,
    uint32_t* __restrict__ out16)
{
    extern __shared__ __align__(128) char sm[];
    const uint32_t sb = smem_u32(sm);
    const uint32_t sQ = sb + SQ_OFF;

    const int tid  = threadIdx.x;
    const int lane = tid & 31;
    const int warp = tid >> 5;
    const int qb   = (int)gridDim.x - 1 - (int)blockIdx.x;
    const int h    = blockIdx.y;
    const int kvg  = h >> 2;

    const int g = lane >> 2, t = lane & 3;
    const int l15 = lane & 15, lh = lane >> 4;

    const char* Qg = (const char*)(qk16 + (size_t)h * 64);          // row stride 5120B
    const char* Kg = (const char*)(qk16 + 1024 + (size_t)kvg * 64); // row stride 5120B
    const char* Vg = (const char*)(v16 + (size_t)kvg * 64);         // row stride 1024B

    // ---- prologue: Q + K0 + V0 via cp.async ----
#pragma unroll
    for (int i = 0; i < 8; i++) {
        int idx = tid + i * 256;
        int row = idx >> 4, u = idx & 15;
        CP_A16(sQ + row * 256 + ((u ^ (row & 7)) << 4),
               Qg + (size_t)(qb * 128 + row) * 5120 + u * 16);
    }
#pragma unroll
    for (int i = 0; i < 4; i++) {
        int idx = tid + i * 256;
        int row = idx >> 4, u = idx & 15;
        uint32_t so = row * 256 + ((u ^ (row & 7)) << 4);
        CP_A16(sb + SK_OFF + so, Kg + (size_t)row * 5120 + u * 16);
        CP_A16(sb + SV_OFF + so, Vg + (size_t)row * 1024 + u * 16);
    }
    CP_COMMIT();

    float oacc[16][4];
#pragma unroll
    for (int i = 0; i < 16; i++)
#pragma unroll
        for (int e = 0; e < 4; e++) oacc[i][e] = 0.f;
    float m0 = -1e30f, m1 = -1e30f, l0 = 0.f, l1 = 0.f;

    const int qr0 = qb * 128 + warp * 16 + g;
    const int ntiles = 2 * qb + 2;

    for (int kt = 0; kt < ntiles; kt++) {
        CP_WAIT(0);
        __syncthreads();

        // issue next tile's K/V into alternate buffers
        if (kt + 1 < ntiles) {
            const uint32_t dK = sb + SK_OFF + ((kt + 1) & 1) * 16384;
            const uint32_t dV = sb + SV_OFF + ((kt + 1) & 1) * 16384;
#pragma unroll
            for (int i = 0; i < 4; i++) {
                int idx = tid + i * 256;
                int row = idx >> 4, u = idx & 15;
                uint32_t so = row * 256 + ((u ^ (row & 7)) << 4);
                CP_A16(dK + so, Kg + (size_t)((kt + 1) * 64 + row) * 5120 + u * 16);
                CP_A16(dV + so, Vg + (size_t)((kt + 1) * 64 + row) * 1024 + u * 16);
            }
            CP_COMMIT();
        }

        const uint32_t cK = sb + SK_OFF + (kt & 1) * 16384;
        const uint32_t cV = sb + SV_OFF + (kt & 1) * 16384;

        // ---- QK: S[m16 x 64] per warp ----
        float acc[8][4];
#pragma unroll
        for (int nt = 0; nt < 8; nt++)
#pragma unroll
            for (int e = 0; e < 4; e++) acc[nt][e] = 0.f;

        const int qrow = warp * 16 + l15;
#pragma unroll
        for (int ki = 0; ki < 8; ki++) {
            uint32_t af[4];
            uint32_t qa = sQ + qrow * 256 + (((ki * 2 + lh) ^ (qrow & 7)) << 4);
            LDSM4(af[0], af[1], af[2], af[3], qa);
#pragma unroll
            for (int ntp = 0; ntp < 4; ntp++) {
                int krow = ntp * 16 + l15;
                uint32_t r0, r1, r2, r3;
                uint32_t ka = cK + krow * 256 + (((ki * 2 + lh) ^ (krow & 7)) << 4);
                LDSM4(r0, r1, r2, r3, ka);
                uint32_t bf0[2] = { r0, r2 };
                uint32_t bf1[2] = { r1, r3 };
                mma_f16(acc[2 * ntp],     af, bf0);
                mma_f16(acc[2 * ntp + 1], af, bf1);
            }
        }

        // ---- softcap + causal ----
        const bool diag = (kt >= 2 * qb);
        float mt0 = -1e30f, mt1 = -1e30f;
#pragma unroll
        for (int nt = 0; nt < 8; nt++) {
#pragma unroll
            for (int e = 0; e < 4; e++) {
                float x = acc[nt][e] * INV_CAP;
                x = fminf(fmaxf(x, -20.f), 20.f);
                float ex = __expf(2.f * x);
                float v = __fdividef(ex - 1.f, ex + 1.f) * CAP;
                if (diag) {
                    int kc = kt * 64 + nt * 8 + 2 * t + (e & 1);
                    int qr = qr0 + ((e >> 1) << 3);
                    if (kc > qr) v = -1e30f;
                }
                acc[nt][e] = v;
                if (e < 2) mt0 = fmaxf(mt0, v); else mt1 = fmaxf(mt1, v);
            }
        }
        mt0 = fmaxf(mt0, __shfl_xor_sync(0xffffffffu, mt0, 1));
        mt0 = fmaxf(mt0, __shfl_xor_sync(0xffffffffu, mt0, 2));
        mt1 = fmaxf(mt1, __shfl_xor_sync(0xffffffffu, mt1, 1));
        mt1 = fmaxf(mt1, __shfl_xor_sync(0xffffffffu, mt1, 2));

        const float mn0 = fmaxf(m0, mt0), mn1 = fmaxf(m1, mt1);
        const float al0 = __expf(m0 - mn0), al1 = __expf(m1 - mn1);
        m0 = mn0; m1 = mn1;

        float rs0 = 0.f, rs1 = 0.f;
#pragma unroll
        for (int nt = 0; nt < 8; nt++) {
            acc[nt][0] = __expf(acc[nt][0] - mn0);
            acc[nt][1] = __expf(acc[nt][1] - mn0);
            acc[nt][2] = __expf(acc[nt][2] - mn1);
            acc[nt][3] = __expf(acc[nt][3] - mn1);
            rs0 += acc[nt][0] + acc[nt][1];
            rs1 += acc[nt][2] + acc[nt][3];
        }
        rs0 += __shfl_xor_sync(0xffffffffu, rs0, 1);
        rs0 += __shfl_xor_sync(0xffffffffu, rs0, 2);
        rs1 += __shfl_xor_sync(0xffffffffu, rs1, 1);
        rs1 += __shfl_xor_sync(0xffffffffu, rs1, 2);
        l0 = l0 * al0 + rs0;
        l1 = l1 * al1 + rs1;

#pragma unroll
        for (int ni = 0; ni < 16; ni++) {
            oacc[ni][0] *= al0; oacc[ni][1] *= al0;
            oacc[ni][2] *= al1; oacc[ni][3] *= al1;
        }

        // ---- P -> smem (natural fp16 rows, warp-private, swizzled) ----
        {
            const uint32_t pwb = SP_OFF + warp * 2048;
#pragma unroll
            for (int nt = 0; nt < 8; nt++) {
                uint32_t a0 = pwb + g * 128 + ((nt ^ (g & 7)) << 4) + t * 4;
                uint32_t a1 = a0 + 8 * 128;
                *(uint32_t*)(sm + a0) = pk(acc[nt][0], acc[nt][1]);
                *(uint32_t*)(sm + a1) = pk(acc[nt][2], acc[nt][3]);
            }
        }
        __syncwarp();

        // ---- PV: O[m16 x 128] += P[m16 x 64] * V[64 x 128] ----
        const uint32_t pwb = sb + SP_OFF + warp * 2048;
        const int prow = l15;
        const int vrl = l15;
#pragma unroll
        for (int ki = 0; ki < 4; ki++) {
            uint32_t af[4];
            uint32_t pa = pwb + prow * 128 + (((ki * 2 + lh) ^ (prow & 7)) << 4);
            LDSM4(af[0], af[1], af[2], af[3], pa);
            const int vrow = ki * 16 + vrl;
            const uint32_t vbase = cV + vrow * 256;
            const int vsw = vrow & 7;
#pragma unroll
            for (int nip = 0; nip < 8; nip++) {
                uint32_t r0, r1, r2, r3;
                uint32_t va = vbase + (((nip * 2 + lh) ^ vsw) << 4);
                LDSM4T(r0, r1, r2, r3, va);
                uint32_t bf0[2] = { r0, r1 };
                uint32_t bf1[2] = { r2, r3 };
                mma_f16(oacc[2 * nip],     af, bf0);
                mma_f16(oacc[2 * nip + 1], af, bf1);
            }
        }
    }

    // ---- epilogue: fp16 output ----
    const float inv0 = __fdividef(1.f, l0);
    const float inv1 = __fdividef(1.f, l1);
    uint32_t* o0 = out16 + (size_t)qr0 * 1024 + h * 64 + t;
    uint32_t* o1 = out16 + (size_t)(qr0 + 8) * 1024 + h * 64 + t;
#pragma unroll
    for (int ni = 0; ni < 16; ni++) {
        o0[ni * 4] = pk(oacc[ni][0] * inv0, oacc[ni][1] * inv0);
        o1[ni * 4] = pk(oacc[ni][2] * inv1, oacc[ni][3] * inv1);
    }
}

// ---------------------------------------------------------------------------
// Inputs (metadata order): hidden_states, cos, sin, attention_mask, wq, wk, wv, wo
// ---------------------------------------------------------------------------
extern "C" void kernel_launch(void* const* d_in, const int* in_sizes, int n_in,
                              void* d_out, int out_size)
{
    const float* hs   = (const float*)d_in[0];
    const float* cosp = (const float*)d_in[1];
    const float* sinp = (const float*)d_in[2];
    const float* wq   = (const float*)d_in[4];
    const float* wk   = (const float*)d_in[5];
    const float* wv   = (const float*)d_in[6];
    const float* wo   = (const float*)d_in[7];
    float* out = (float*)d_out;

    float* qkv = nullptr; uint32_t* qk16 = nullptr; uint32_t* v16 = nullptr;
    uint32_t* hs16 = nullptr; uint32_t* w16 = nullptr;
    uint32_t* wo16 = nullptr; uint32_t* attn16 = nullptr;
    cudaGetSymbolAddress((void**)&qkv,    g_qkv);
    cudaGetSymbolAddress((void**)&qk16,   g_qk16);
    cudaGetSymbolAddress((void**)&v16,    g_v16);
    cudaGetSymbolAddress((void**)&hs16,   g_hs16);
    cudaGetSymbolAddress((void**)&w16,    g_w16);
    cudaGetSymbolAddress((void**)&wo16,   g_wo16);
    cudaGetSymbolAddress((void**)&attn16, g_attn16);

    cudaFuncSetAttribute(gemm_h, cudaFuncAttributeMaxDynamicSharedMemorySize, GEMM_SMEM);
    cudaFuncSetAttribute(attn_mma, cudaFuncAttributeMaxDynamicSharedMemorySize, ATTN_SMEM);

    dim3 blk(256);
    cvt16<<<(S_LEN * HID / 4 + 255) / 256, blk>>>(hs, hs16, S_LEN * HID / 4);
    cvt16<<<(2048 * HID / 4 + 255) / 256, blk>>>(wq, w16, 2048 * HID / 4);
    cvt16<<<(512 * HID / 4 + 255) / 256, blk>>>(wk, w16 + (size_t)2048 * 1024, 512 * HID / 4);
    cvt16<<<(512 * HID / 4 + 255) / 256, blk>>>(wv, w16 + (size_t)2560 * 1024, 512 * HID / 4);
    cvt16<<<(2048 * HID / 4 + 255) / 256, blk>>>(wo, wo16, 2048 * HID / 4);

    gemm_h<<<dim3(3072 / 64, S_LEN / 128), blk, GEMM_SMEM>>>(
        (const __half*)hs16, (const __half*)w16, qkv, HID, QKV_LD);
    rope_pack<<<S_LEN, 256>>>(qkv, qk16, v16, cosp, sinp);
    attn_mma<<<dim3(S_LEN / 128, NH), blk, ATTN_SMEM>>>(qk16, v16, attn16);
    gemm_h<<<dim3(2048 / 64, S_LEN / 128), blk, GEMM_SMEM>>>(
        (const __half*)attn16, (const __half*)wo16, out, HID, HID);
}